// round 1
// baseline (speedup 1.0000x reference)
#include <cuda_runtime.h>
#include <cstdint>

#define BN 4
#define CC 256
#define NN 4096
#define CQ 32

// ---------------- scratch (static __device__, no allocs) ----------------
__device__ float    g_q[BN * CQ * NN];            // [b][cq][n] fp32
__device__ float    g_k[BN * CQ * NN];            // [b][cq][n] fp32
__device__ unsigned g_vtp[BN * (NN / 2) * CC];    // [b][m2][c], u32 = (bf16 v[c][2m2+1]<<16)|bf16 v[c][2m2]
__device__ float    g_zpart[BN * NN * 32];        // [b][j][itile]
__device__ float    g_rz[BN * NN];                // 1/Z per row j

__device__ __forceinline__ unsigned bf16bits(float f) {
    unsigned u = __float_as_uint(f);
    return (u + 0x7fffu + ((u >> 16) & 1u)) >> 16;
}

// ---------------- K1a: q,k = W{q,k} @ x + b ----------------
// grid (32 nblk, 4 b), 256 thr. tile 64 rows (32 q + 32 k) x 128 n, K=256.
__global__ void __launch_bounds__(256) k_qk(const float* __restrict__ x,
                                            const float* __restrict__ Wq, const float* __restrict__ bq,
                                            const float* __restrict__ Wk, const float* __restrict__ bk) {
    __shared__ float Ws[64][33];
    __shared__ float Xs[32][128];
    int b = blockIdx.y;
    int n0 = blockIdx.x * 128;
    int tid = threadIdx.x;
    const float* xb = x + (size_t)b * CC * NN;
    float acc[4][8];
#pragma unroll
    for (int i = 0; i < 4; i++)
#pragma unroll
        for (int j = 0; j < 8; j++) acc[i][j] = 0.f;
    int tr = tid >> 4, tn = tid & 15;
    for (int k0 = 0; k0 < CC; k0 += 32) {
        for (int i = tid; i < 64 * 32; i += 256) {
            int r = i >> 5, kk = i & 31;
            Ws[r][kk] = (r < 32) ? Wq[r * CC + k0 + kk] : Wk[(r - 32) * CC + k0 + kk];
        }
        for (int i = tid * 4; i < 32 * 128; i += 1024) {
            int kk = i >> 7, nn = i & 127;
            *(float4*)&Xs[kk][nn] = *(const float4*)&xb[(size_t)(k0 + kk) * NN + n0 + nn];
        }
        __syncthreads();
#pragma unroll
        for (int kk = 0; kk < 32; kk++) {
            float wf[4], xf[8];
#pragma unroll
            for (int i = 0; i < 4; i++) wf[i] = Ws[tr * 4 + i][kk];
            *(float4*)&xf[0] = *(float4*)&Xs[kk][tn * 8];
            *(float4*)&xf[4] = *(float4*)&Xs[kk][tn * 8 + 4];
#pragma unroll
            for (int i = 0; i < 4; i++)
#pragma unroll
                for (int j = 0; j < 8; j++) acc[i][j] += wf[i] * xf[j];
        }
        __syncthreads();
    }
#pragma unroll
    for (int i = 0; i < 4; i++) {
        int r = tr * 4 + i;
        float bias = (r < 32) ? bq[r] : bk[r - 32];
        float* dst = (r < 32) ? (g_q + ((size_t)b * CQ + r) * NN)
                              : (g_k + ((size_t)b * CQ + (r - 32)) * NN);
        dst += n0 + tn * 8;
        float4 o0 = {acc[i][0] + bias, acc[i][1] + bias, acc[i][2] + bias, acc[i][3] + bias};
        float4 o1 = {acc[i][4] + bias, acc[i][5] + bias, acc[i][6] + bias, acc[i][7] + bias};
        *(float4*)dst = o0;
        *(float4*)(dst + 4) = o1;
    }
}

// ---------------- K1b: v = Wv @ x + bv, stored transposed bf16-pair-packed ----------------
// grid (32 nblk, 4 cblk, 4 b), 256 thr. tile 64 c x 128 n.
__global__ void __launch_bounds__(256) k_v(const float* __restrict__ x,
                                           const float* __restrict__ Wv, const float* __restrict__ bv) {
    __shared__ float Ws[64][33];
    __shared__ float Xs[32][128];
    unsigned* tsh = (unsigned*)&Xs[0][0];  // 32x64 u32 transpose staging (reused after GEMM)
    int nb = blockIdx.x, cb = blockIdx.y, b = blockIdx.z;
    int n0 = nb * 128, c0 = cb * 64;
    int tid = threadIdx.x;
    const float* xb = x + (size_t)b * CC * NN;
    float acc[4][8];
#pragma unroll
    for (int i = 0; i < 4; i++)
#pragma unroll
        for (int j = 0; j < 8; j++) acc[i][j] = 0.f;
    int tr = tid >> 4, tn = tid & 15;
    for (int k0 = 0; k0 < CC; k0 += 32) {
        for (int i = tid; i < 64 * 32; i += 256) {
            int r = i >> 5, kk = i & 31;
            Ws[r][kk] = Wv[(size_t)(c0 + r) * CC + k0 + kk];
        }
        for (int i = tid * 4; i < 32 * 128; i += 1024) {
            int kk = i >> 7, nn = i & 127;
            *(float4*)&Xs[kk][nn] = *(const float4*)&xb[(size_t)(k0 + kk) * NN + n0 + nn];
        }
        __syncthreads();
#pragma unroll
        for (int kk = 0; kk < 32; kk++) {
            float wf[4], xf[8];
#pragma unroll
            for (int i = 0; i < 4; i++) wf[i] = Ws[tr * 4 + i][kk];
            *(float4*)&xf[0] = *(float4*)&Xs[kk][tn * 8];
            *(float4*)&xf[4] = *(float4*)&Xs[kk][tn * 8 + 4];
#pragma unroll
            for (int i = 0; i < 4; i++)
#pragma unroll
                for (int j = 0; j < 8; j++) acc[i][j] += wf[i] * xf[j];
        }
        __syncthreads();
    }
#pragma unroll
    for (int i = 0; i < 4; i++) {
        float bias = bv[c0 + tr * 4 + i];
#pragma unroll
        for (int j = 0; j < 8; j++) acc[i][j] += bias;
    }
    // transpose + pack bf16 pairs, two n-halves of 64
    for (int h = 0; h < 2; h++) {
        __syncthreads();
        if ((tn >> 3) == h) {
#pragma unroll
            for (int i = 0; i < 4; i++) {
#pragma unroll
                for (int p = 0; p < 4; p++) {
                    unsigned pk = bf16bits(acc[i][2 * p]) | (bf16bits(acc[i][2 * p + 1]) << 16);
                    tsh[(tn * 4 + p - h * 32) * 64 + (tr * 4 + i)] = pk;
                }
            }
        }
        __syncthreads();
        int r = tid >> 3, cc = (tid & 7) * 8;
        uint4 v0 = *(uint4*)&tsh[r * 64 + cc];
        uint4 v1 = *(uint4*)&tsh[r * 64 + cc + 4];
        unsigned* dst = g_vtp + ((size_t)b * (NN / 2) + nb * 64 + h * 32 + r) * CC + c0 + cc;
        *(uint4*)dst = v0;
        *(uint4*)(dst + 4) = v1;
    }
}

// ---------------- K2: E[j][i] = exp(sum_c k[c][j] q[c][i]); row partial sums ----------------
// grid (32 iblk, 32 jblk, 4 b), 256 thr, tile 128x128.
__global__ void __launch_bounds__(256) k_s(float* __restrict__ E) {
    __shared__ float ks[32][128];
    __shared__ float qs[32][128];
    __shared__ float zs[128];
    int ibk = blockIdx.x, jbk = blockIdx.y, b = blockIdx.z;
    int i0 = ibk * 128, j0 = jbk * 128;
    int tid = threadIdx.x;
    if (tid < 128) zs[tid] = 0.f;
    for (int i = tid * 4; i < 32 * 128; i += 1024) {
        int c = i >> 7, jj = i & 127;
        *(float4*)&ks[c][jj] = *(const float4*)&g_k[((size_t)b * CQ + c) * NN + j0 + jj];
        *(float4*)&qs[c][jj] = *(const float4*)&g_q[((size_t)b * CQ + c) * NN + i0 + jj];
    }
    __syncthreads();
    float acc[8][8];
#pragma unroll
    for (int r = 0; r < 8; r++)
#pragma unroll
        for (int q = 0; q < 8; q++) acc[r][q] = 0.f;
    int tj = tid >> 4, ti = tid & 15;
#pragma unroll
    for (int c = 0; c < 32; c++) {
        float kf[8], qf[8];
        *(float4*)&kf[0] = *(float4*)&ks[c][tj * 8];
        *(float4*)&kf[4] = *(float4*)&ks[c][tj * 8 + 4];
        *(float4*)&qf[0] = *(float4*)&qs[c][ti * 8];
        *(float4*)&qf[4] = *(float4*)&qs[c][ti * 8 + 4];
#pragma unroll
        for (int r = 0; r < 8; r++)
#pragma unroll
            for (int q = 0; q < 8; q++) acc[r][q] += kf[r] * qf[q];
    }
    float* Eb = E + ((size_t)b * NN + j0) * (size_t)NN + i0;
#pragma unroll
    for (int r = 0; r < 8; r++) {
        int j = tj * 8 + r;
        float4 e0, e1;
        e0.x = __expf(acc[r][0]); e0.y = __expf(acc[r][1]);
        e0.z = __expf(acc[r][2]); e0.w = __expf(acc[r][3]);
        e1.x = __expf(acc[r][4]); e1.y = __expf(acc[r][5]);
        e1.z = __expf(acc[r][6]); e1.w = __expf(acc[r][7]);
        *(float4*)&Eb[(size_t)j * NN + ti * 8] = e0;
        *(float4*)&Eb[(size_t)j * NN + ti * 8 + 4] = e1;
        float s = e0.x + e0.y + e0.z + e0.w + e1.x + e1.y + e1.z + e1.w;
        atomicAdd(&zs[j], s);
    }
    __syncthreads();
    if (tid < 128)
        g_zpart[((size_t)b * NN + j0 + tid) * 32 + ibk] = zs[tid];
}

// ---------------- K2b: rZ = 1 / sum(partials) ----------------
__global__ void __launch_bounds__(256) k_rz() {
    int idx = blockIdx.x * 256 + threadIdx.x;  // < BN*NN
    const float4* p = (const float4*)&g_zpart[(size_t)idx * 32];
    float s = 0.f;
#pragma unroll
    for (int i = 0; i < 8; i++) { float4 v = p[i]; s += v.x + v.y + v.z + v.w; }
    g_rz[idx] = 1.f / s;
}

// ---------------- K3: normalize AM in place + o^T = P @ v^T (bf16 mma.sync) + out = x + g*o ----------------
__device__ __forceinline__ void mma16816(float* d, unsigned a0, unsigned a1, unsigned a2, unsigned a3,
                                         unsigned b0, unsigned b1) {
    asm volatile(
        "mma.sync.aligned.m16n8k16.row.col.f32.bf16.bf16.f32 "
        "{%0,%1,%2,%3}, {%4,%5,%6,%7}, {%8,%9}, {%0,%1,%2,%3};\n"
        : "+f"(d[0]), "+f"(d[1]), "+f"(d[2]), "+f"(d[3])
        : "r"(a0), "r"(a1), "r"(a2), "r"(a3), "r"(b0), "r"(b1));
}

// grid (64 jb, 4 b), 256 thr. CTA tile: 64 j x 256 c, k-loop over m in chunks of 64.
__global__ void __launch_bounds__(256) k_o(float* __restrict__ E, const float* __restrict__ x,
                                           const float* __restrict__ gptr, float* __restrict__ outp) {
    __shared__ unsigned As[64 * 36];   // bf16 P tile, row stride 36 u32 (conflict-free frag loads)
    __shared__ unsigned Bs[32 * 260];  // packed v^T chunk [m2][c], row stride 260 u32
    __shared__ float rzs[64];
    int jb = blockIdx.x, b = blockIdx.y;
    int j0 = jb * 64;
    int tid = threadIdx.x;
    if (tid < 64) rzs[tid] = g_rz[(size_t)b * NN + j0 + tid];
    __syncthreads();
    int warp = tid >> 5, lane = tid & 31;
    int wj = warp >> 2, wc = warp & 3, gid = lane >> 2, tg = lane & 3;
    float acc[2][8][4];
#pragma unroll
    for (int a = 0; a < 2; a++)
#pragma unroll
        for (int n = 0; n < 8; n++)
#pragma unroll
            for (int c = 0; c < 4; c++) acc[a][n][c] = 0.f;
    float* Erow = E + ((size_t)b * NN + j0) * (size_t)NN;
    const unsigned* vb = g_vtp + (size_t)b * (NN / 2) * CC;
    int ar = tid >> 2, acq = (tid & 3) * 8;  // row / u32-col offset in A stage
    float myrz = rzs[ar];

    for (int m0 = 0; m0 < NN; m0 += 64) {
        // ---- A stage: read E, scale (final AM write-back), pack bf16 ----
        float* ep = Erow + (size_t)ar * NN + m0 + acq * 2;
        unsigned pk[8];
#pragma unroll
        for (int g4 = 0; g4 < 4; g4++) {
            float4 v = *(float4*)(ep + g4 * 4);
            v.x *= myrz; v.y *= myrz; v.z *= myrz; v.w *= myrz;
            *(float4*)(ep + g4 * 4) = v;
            pk[g4 * 2]     = bf16bits(v.x) | (bf16bits(v.y) << 16);
            pk[g4 * 2 + 1] = bf16bits(v.z) | (bf16bits(v.w) << 16);
        }
        *(uint4*)&As[ar * 36 + acq]     = *(uint4*)&pk[0];
        *(uint4*)&As[ar * 36 + acq + 4] = *(uint4*)&pk[4];
        // ---- B stage: v^T packed chunk ----
        {
            int r = tid >> 3, cc = (tid & 7) * 32;
            const uint4* src = (const uint4*)(vb + ((size_t)(m0 >> 1) + r) * CC + cc);
#pragma unroll
            for (int q = 0; q < 8; q++)
                *(uint4*)&Bs[r * 260 + cc + q * 4] = src[q];
        }
        __syncthreads();
#pragma unroll
        for (int kk = 0; kk < 4; kk++) {
            unsigned a[2][4];
#pragma unroll
            for (int jt = 0; jt < 2; jt++) {
                int r0 = wj * 32 + jt * 16;
                a[jt][0] = As[(r0 + gid) * 36     + kk * 8 + tg];
                a[jt][1] = As[(r0 + gid + 8) * 36 + kk * 8 + tg];
                a[jt][2] = As[(r0 + gid) * 36     + kk * 8 + tg + 4];
                a[jt][3] = As[(r0 + gid + 8) * 36 + kk * 8 + tg + 4];
            }
#pragma unroll
            for (int nt = 0; nt < 8; nt++) {
                unsigned b0 = Bs[(kk * 8 + tg) * 260     + wc * 64 + nt * 8 + gid];
                unsigned b1 = Bs[(kk * 8 + tg + 4) * 260 + wc * 64 + nt * 8 + gid];
                mma16816(acc[0][nt], a[0][0], a[0][1], a[0][2], a[0][3], b0, b1);
                mma16816(acc[1][nt], a[1][0], a[1][1], a[1][2], a[1][3], b0, b1);
            }
        }
        __syncthreads();
    }
    // ---- epilogue: smem transpose, out = x + gamma*o ----
    float gma = __ldg(gptr);
    float* fBs = (float*)Bs;  // 32x256 fp32 staging
    for (int h = 0; h < 2; h++) {
        if (wj == h) {
#pragma unroll
            for (int jt = 0; jt < 2; jt++)
#pragma unroll
                for (int nt = 0; nt < 8; nt++) {
                    int rr = jt * 16 + gid;
                    int cc2 = wc * 64 + nt * 8 + tg * 2;
                    fBs[rr * 256 + cc2]           = acc[jt][nt][0];
                    fBs[rr * 256 + cc2 + 1]       = acc[jt][nt][1];
                    fBs[(rr + 8) * 256 + cc2]     = acc[jt][nt][2];
                    fBs[(rr + 8) * 256 + cc2 + 1] = acc[jt][nt][3];
                }
        }
        __syncthreads();
        int c = tid;
        const float* xrow = x + ((size_t)b * CC + c) * NN + j0 + h * 32;
        float* orow = outp + ((size_t)b * CC + c) * NN + j0 + h * 32;
#pragma unroll
        for (int jq = 0; jq < 8; jq++) {
            float4 o;
            o.x = fBs[(jq * 4 + 0) * 256 + c];
            o.y = fBs[(jq * 4 + 1) * 256 + c];
            o.z = fBs[(jq * 4 + 2) * 256 + c];
            o.w = fBs[(jq * 4 + 3) * 256 + c];
            float4 xr = *(const float4*)(xrow + jq * 4);
            float4 res = {xr.x + gma * o.x, xr.y + gma * o.y, xr.z + gma * o.z, xr.w + gma * o.w};
            *(float4*)(orow + jq * 4) = res;
        }
        __syncthreads();
    }
}

// ---------------- launch ----------------
extern "C" void kernel_launch(void* const* d_in, const int* in_sizes, int n_in,
                              void* d_out, int out_size) {
    const float* x  = (const float*)d_in[0];
    const float* Wq = (const float*)d_in[1];
    const float* bq = (const float*)d_in[2];
    const float* Wk = (const float*)d_in[3];
    const float* bk = (const float*)d_in[4];
    const float* Wv = (const float*)d_in[5];
    const float* bv = (const float*)d_in[6];
    const float* gm = (const float*)d_in[7];
    float* outp = (float*)d_out;
    float* AM = outp + (size_t)BN * CC * 64 * 64;  // attention_map region

    k_qk<<<dim3(32, BN), 256>>>(x, Wq, bq, Wk, bk);
    k_v<<<dim3(32, 4, BN), 256>>>(x, Wv, bv);
    k_s<<<dim3(32, 32, BN), 256>>>(AM);
    k_rz<<<(BN * NN) / 256, 256>>>();
    k_o<<<dim3(64, BN), 256>>>(AM, x, gm, outp);
}

// round 3
// speedup vs baseline: 1.1798x; 1.1798x over previous
#include <cuda_runtime.h>
#include <cstdint>

#define BN 4
#define CC 256
#define NN 4096
#define CQ 32

// ---------------- scratch ----------------
__device__ unsigned g_qh[BN * NN * 16];         // [b][n][cw] hi bf16 pair (c even/odd packed)
__device__ unsigned g_ql[BN * NN * 16];         // lo residual
__device__ unsigned g_kh[BN * NN * 16];
__device__ unsigned g_kl[BN * NN * 16];
__device__ unsigned g_vtp[BN * (NN / 2) * CC];  // [b][m2][c] = pack(v[c][2m2], v[c][2m2+1])
__device__ float    g_rz[BN * NN];              // 1/Z per AM row j

__device__ __forceinline__ unsigned bf16bits(float f) {
    unsigned u = __float_as_uint(f);
    return (u + 0x7fffu + ((u >> 16) & 1u)) >> 16;
}

__device__ __forceinline__ void mma16816(float* d, unsigned a0, unsigned a1, unsigned a2, unsigned a3,
                                         unsigned b0, unsigned b1) {
    asm volatile(
        "mma.sync.aligned.m16n8k16.row.col.f32.bf16.bf16.f32 "
        "{%0,%1,%2,%3}, {%4,%5,%6,%7}, {%8,%9}, {%0,%1,%2,%3};\n"
        : "+f"(d[0]), "+f"(d[1]), "+f"(d[2]), "+f"(d[3])
        : "r"(a0), "r"(a1), "r"(a2), "r"(a3), "r"(b0), "r"(b1));
}

// ---------------- K1a: q,k = W{q,k} @ x + b, emitted transposed + bf16 hi/lo split ----------------
// grid (32 nblk, 4 b), 256 thr. tile 64 rows (32 q + 32 k) x 128 n, K=256.
__global__ void __launch_bounds__(256) k_qk(const float* __restrict__ x,
                                            const float* __restrict__ Wq, const float* __restrict__ bq,
                                            const float* __restrict__ Wk, const float* __restrict__ bk) {
    __shared__ float Ws[64][33];
    __shared__ float Xs[32][128];
    int b = blockIdx.y;
    int n0 = blockIdx.x * 128;
    int tid = threadIdx.x;
    const float* xb = x + (size_t)b * CC * NN;
    float acc[4][8];
#pragma unroll
    for (int i = 0; i < 4; i++)
#pragma unroll
        for (int j = 0; j < 8; j++) acc[i][j] = 0.f;
    int tr = tid >> 4, tn = tid & 15;
    for (int k0 = 0; k0 < CC; k0 += 32) {
        for (int i = tid; i < 64 * 32; i += 256) {
            int r = i >> 5, kk = i & 31;
            Ws[r][kk] = (r < 32) ? Wq[r * CC + k0 + kk] : Wk[(r - 32) * CC + k0 + kk];
        }
        for (int i = tid * 4; i < 32 * 128; i += 1024) {
            int kk = i >> 7, nn = i & 127;
            *(float4*)&Xs[kk][nn] = *(const float4*)&xb[(size_t)(k0 + kk) * NN + n0 + nn];
        }
        __syncthreads();
#pragma unroll
        for (int kk = 0; kk < 32; kk++) {
            float wf[4], xf[8];
#pragma unroll
            for (int i = 0; i < 4; i++) wf[i] = Ws[tr * 4 + i][kk];
            *(float4*)&xf[0] = *(float4*)&Xs[kk][tn * 8];
            *(float4*)&xf[4] = *(float4*)&Xs[kk][tn * 8 + 4];
#pragma unroll
            for (int i = 0; i < 4; i++)
#pragma unroll
                for (int j = 0; j < 8; j++) acc[i][j] += wf[i] * xf[j];
        }
        __syncthreads();
    }
    // bias add
#pragma unroll
    for (int i = 0; i < 4; i++) {
        int r = tr * 4 + i;
        float bias = (r < 32) ? bq[r] : bk[r - 32];
#pragma unroll
        for (int j = 0; j < 8; j++) acc[i][j] += bias;
    }
    // split into hi/lo packed words (c-pairs)
    unsigned hw[2][8], lw[2][8];
#pragma unroll
    for (int p = 0; p < 2; p++)
#pragma unroll
        for (int j = 0; j < 8; j++) {
            float a0 = acc[2 * p][j], a1 = acc[2 * p + 1][j];
            unsigned h0 = bf16bits(a0);
            unsigned h1 = bf16bits(a1);
            float f0 = __uint_as_float(h0 << 16);
            float f1 = __uint_as_float(h1 << 16);
            unsigned l0 = bf16bits(a0 - f0);
            unsigned l1 = bf16bits(a1 - f1);
            hw[p][j] = h0 | (h1 << 16);
            lw[p][j] = l0 | (l1 << 16);
        }
    unsigned* st = (unsigned*)&Xs[0][0];  // 128 x 17 staging
    bool isq = (tr < 8);
    int cw0 = (isq ? tr : tr - 8) * 2;
    unsigned* outs0 = g_qh; unsigned* outs1 = g_ql;
    unsigned* outs2 = g_kh; unsigned* outs3 = g_kl;
    for (int ph = 0; ph < 4; ph++) {
        bool mine = (ph < 2) ? isq : !isq;
        bool lo = (ph & 1);
        __syncthreads();
        if (mine) {
#pragma unroll
            for (int p = 0; p < 2; p++)
#pragma unroll
                for (int j = 0; j < 8; j++)
                    st[(tn * 8 + j) * 17 + cw0 + p] = lo ? lw[p][j] : hw[p][j];
        }
        __syncthreads();
        unsigned* dst = (ph == 0 ? outs0 : ph == 1 ? outs1 : ph == 2 ? outs2 : outs3)
                        + ((size_t)b * NN + n0) * 16;
        int row = tid >> 1, w0 = (tid & 1) * 8;
        unsigned t0 = st[row * 17 + w0 + 0], t1 = st[row * 17 + w0 + 1];
        unsigned t2 = st[row * 17 + w0 + 2], t3 = st[row * 17 + w0 + 3];
        unsigned t4 = st[row * 17 + w0 + 4], t5 = st[row * 17 + w0 + 5];
        unsigned t6 = st[row * 17 + w0 + 6], t7 = st[row * 17 + w0 + 7];
        *(uint4*)&dst[row * 16 + w0] = make_uint4(t0, t1, t2, t3);
        *(uint4*)&dst[row * 16 + w0 + 4] = make_uint4(t4, t5, t6, t7);
    }
}

// ---------------- K1b: v = Wv @ x + bv, stored transposed bf16-pair-packed ----------------
__global__ void __launch_bounds__(256) k_v(const float* __restrict__ x,
                                           const float* __restrict__ Wv, const float* __restrict__ bv) {
    __shared__ float Ws[64][33];
    __shared__ float Xs[32][128];
    unsigned* tsh = (unsigned*)&Xs[0][0];
    int nb = blockIdx.x, cb = blockIdx.y, b = blockIdx.z;
    int n0 = nb * 128, c0 = cb * 64;
    int tid = threadIdx.x;
    const float* xb = x + (size_t)b * CC * NN;
    float acc[4][8];
#pragma unroll
    for (int i = 0; i < 4; i++)
#pragma unroll
        for (int j = 0; j < 8; j++) acc[i][j] = 0.f;
    int tr = tid >> 4, tn = tid & 15;
    for (int k0 = 0; k0 < CC; k0 += 32) {
        for (int i = tid; i < 64 * 32; i += 256) {
            int r = i >> 5, kk = i & 31;
            Ws[r][kk] = Wv[(size_t)(c0 + r) * CC + k0 + kk];
        }
        for (int i = tid * 4; i < 32 * 128; i += 1024) {
            int kk = i >> 7, nn = i & 127;
            *(float4*)&Xs[kk][nn] = *(const float4*)&xb[(size_t)(k0 + kk) * NN + n0 + nn];
        }
        __syncthreads();
#pragma unroll
        for (int kk = 0; kk < 32; kk++) {
            float wf[4], xf[8];
#pragma unroll
            for (int i = 0; i < 4; i++) wf[i] = Ws[tr * 4 + i][kk];
            *(float4*)&xf[0] = *(float4*)&Xs[kk][tn * 8];
            *(float4*)&xf[4] = *(float4*)&Xs[kk][tn * 8 + 4];
#pragma unroll
            for (int i = 0; i < 4; i++)
#pragma unroll
                for (int j = 0; j < 8; j++) acc[i][j] += wf[i] * xf[j];
        }
        __syncthreads();
    }
#pragma unroll
    for (int i = 0; i < 4; i++) {
        float bias = bv[c0 + tr * 4 + i];
#pragma unroll
        for (int j = 0; j < 8; j++) acc[i][j] += bias;
    }
    for (int h = 0; h < 2; h++) {
        __syncthreads();
        if ((tn >> 3) == h) {
#pragma unroll
            for (int i = 0; i < 4; i++) {
#pragma unroll
                for (int p = 0; p < 4; p++) {
                    unsigned pk = bf16bits(acc[i][2 * p]) | (bf16bits(acc[i][2 * p + 1]) << 16);
                    tsh[(tn * 4 + p - h * 32) * 64 + (tr * 4 + i)] = pk;
                }
            }
        }
        __syncthreads();
        int r = tid >> 3, cc = (tid & 7) * 8;
        uint4 v0 = *(uint4*)&tsh[r * 64 + cc];
        uint4 v1 = *(uint4*)&tsh[r * 64 + cc + 4];
        unsigned* dst = g_vtp + ((size_t)b * (NN / 2) + nb * 64 + h * 32 + r) * CC + c0 + cc;
        *(uint4*)dst = v0;
        *(uint4*)(dst + 4) = v1;
    }
}

// ---------------- KZ: rz[j] = 1 / sum_i exp(s[i,j]) via tensor-core S recompute ----------------
// grid (64 jb, 4 b), 256 thr. CTA: 64 j rows, loop i in chunks of 64.
__global__ void __launch_bounds__(256) k_z() {
    __shared__ unsigned ksh[64 * 20], ksl[64 * 20];
    __shared__ unsigned qsh[64 * 20], qsl[64 * 20];
    __shared__ float zsh[64];
    int jb = blockIdx.x, b = blockIdx.y;
    int j0 = jb * 64;
    int tid = threadIdx.x;
    if (tid < 64) zsh[tid] = 0.f;
    {
        int r = tid >> 2, w = (tid & 3) * 4;
        *(uint4*)&ksh[r * 20 + w] = *(const uint4*)&g_kh[((size_t)b * NN + j0 + r) * 16 + w];
        *(uint4*)&ksl[r * 20 + w] = *(const uint4*)&g_kl[((size_t)b * NN + j0 + r) * 16 + w];
    }
    int warp = tid >> 5, lane = tid & 31, gid = lane >> 2, tg = lane & 3;
    int j0s = (warp & 3) * 16, m0s = (warp >> 2) * 32;
    float z0 = 0.f, z1 = 0.f;
    int r = tid >> 2, w = (tid & 3) * 4;
    for (int i0 = 0; i0 < NN; i0 += 64) {
        __syncthreads();
        *(uint4*)&qsh[r * 20 + w] = *(const uint4*)&g_qh[((size_t)b * NN + i0 + r) * 16 + w];
        *(uint4*)&qsl[r * 20 + w] = *(const uint4*)&g_ql[((size_t)b * NN + i0 + r) * 16 + w];
        __syncthreads();
        float d[4][4];
#pragma unroll
        for (int t = 0; t < 4; t++)
#pragma unroll
            for (int e = 0; e < 4; e++) d[t][e] = 0.f;
#pragma unroll
        for (int kk2 = 0; kk2 < 2; kk2++) {
            int ar = (j0s + gid) * 20 + kk2 * 8 + tg;
            unsigned ah0 = ksh[ar], ah1 = ksh[ar + 160], ah2 = ksh[ar + 4], ah3 = ksh[ar + 164];
            unsigned al0 = ksl[ar], al1 = ksl[ar + 160], al2 = ksl[ar + 4], al3 = ksl[ar + 164];
#pragma unroll
            for (int t = 0; t < 4; t++) {
                int br = (m0s + t * 8 + gid) * 20 + kk2 * 8 + tg;
                unsigned bh0 = qsh[br], bh1 = qsh[br + 4];
                unsigned bl0 = qsl[br], bl1 = qsl[br + 4];
                mma16816(d[t], ah0, ah1, ah2, ah3, bh0, bh1);
                mma16816(d[t], ah0, ah1, ah2, ah3, bl0, bl1);
                mma16816(d[t], al0, al1, al2, al3, bh0, bh1);
            }
        }
#pragma unroll
        for (int t = 0; t < 4; t++) {
            z0 += __expf(d[t][0]) + __expf(d[t][1]);
            z1 += __expf(d[t][2]) + __expf(d[t][3]);
        }
    }
    z0 += __shfl_xor_sync(0xffffffffu, z0, 1);
    z0 += __shfl_xor_sync(0xffffffffu, z0, 2);
    z1 += __shfl_xor_sync(0xffffffffu, z1, 1);
    z1 += __shfl_xor_sync(0xffffffffu, z1, 2);
    if (tg == 0) {
        atomicAdd(&zsh[j0s + gid], z0);
        atomicAdd(&zsh[j0s + gid + 8], z1);
    }
    __syncthreads();
    if (tid < 64) g_rz[(size_t)b * NN + j0 + tid] = 1.f / zsh[tid];
}

// ---------------- KO: fused S recompute + normalize + AM write + o = P @ v^T + residual ----------------
// grid (64 jb, 4 b), 256 thr, dynamic smem.
struct KoSmem {
    unsigned ksh[64 * 20];
    unsigned ksl[64 * 20];
    unsigned qsh[64 * 20];
    unsigned qsl[64 * 20];
    unsigned As[64 * 36];
    unsigned Bs[32 * 260];
    float rzs[64];
};

__global__ void __launch_bounds__(256) k_o2(float* __restrict__ AM, const float* __restrict__ x,
                                            const float* __restrict__ gptr, float* __restrict__ outp) {
    extern __shared__ KoSmem sm[];
    KoSmem& S = sm[0];
    int jb = blockIdx.x, b = blockIdx.y;
    int j0 = jb * 64;
    int tid = threadIdx.x;
    if (tid < 64) S.rzs[tid] = g_rz[(size_t)b * NN + j0 + tid];
    {
        int r = tid >> 2, w = (tid & 3) * 4;
        *(uint4*)&S.ksh[r * 20 + w] = *(const uint4*)&g_kh[((size_t)b * NN + j0 + r) * 16 + w];
        *(uint4*)&S.ksl[r * 20 + w] = *(const uint4*)&g_kl[((size_t)b * NN + j0 + r) * 16 + w];
    }
    __syncthreads();
    int warp = tid >> 5, lane = tid & 31, gid = lane >> 2, tg = lane & 3;
    // S-stage roles
    int j0s = (warp & 3) * 16, m0s = (warp >> 2) * 32;
    float rz0 = S.rzs[j0s + gid], rz1 = S.rzs[j0s + gid + 8];
    // o-stage roles
    int wj = warp >> 2, wc = warp & 3;
    float acc[2][8][4];
#pragma unroll
    for (int a = 0; a < 2; a++)
#pragma unroll
        for (int n = 0; n < 8; n++)
#pragma unroll
            for (int c = 0; c < 4; c++) acc[a][n][c] = 0.f;
    float* AMrow = AM + ((size_t)b * NN + j0) * (size_t)NN;
    const unsigned* vb = g_vtp + (size_t)b * (NN / 2) * CC;
    int lr = tid >> 2, lw = (tid & 3) * 4;

    for (int m0 = 0; m0 < NN; m0 += 64) {
        // ---- loads: q chunk + v chunk ----
        *(uint4*)&S.qsh[lr * 20 + lw] = *(const uint4*)&g_qh[((size_t)b * NN + m0 + lr) * 16 + lw];
        *(uint4*)&S.qsl[lr * 20 + lw] = *(const uint4*)&g_ql[((size_t)b * NN + m0 + lr) * 16 + lw];
        {
            int r = tid >> 3, cc = (tid & 7) * 32;
            const uint4* src = (const uint4*)(vb + ((size_t)(m0 >> 1) + r) * CC + cc);
#pragma unroll
            for (int q = 0; q < 8; q++)
                *(uint4*)&S.Bs[r * 260 + cc + q * 4] = src[q];
        }
        __syncthreads();
        // ---- S-stage: tensor-core s, exp, normalize, AM write, As(bf16 P) write ----
        float d[4][4];
#pragma unroll
        for (int t = 0; t < 4; t++)
#pragma unroll
            for (int e = 0; e < 4; e++) d[t][e] = 0.f;
#pragma unroll
        for (int kk2 = 0; kk2 < 2; kk2++) {
            int ar = (j0s + gid) * 20 + kk2 * 8 + tg;
            unsigned ah0 = S.ksh[ar], ah1 = S.ksh[ar + 160], ah2 = S.ksh[ar + 4], ah3 = S.ksh[ar + 164];
            unsigned al0 = S.ksl[ar], al1 = S.ksl[ar + 160], al2 = S.ksl[ar + 4], al3 = S.ksl[ar + 164];
#pragma unroll
            for (int t = 0; t < 4; t++) {
                int br = (m0s + t * 8 + gid) * 20 + kk2 * 8 + tg;
                unsigned bh0 = S.qsh[br], bh1 = S.qsh[br + 4];
                unsigned bl0 = S.qsl[br], bl1 = S.qsl[br + 4];
                mma16816(d[t], ah0, ah1, ah2, ah3, bh0, bh1);
                mma16816(d[t], ah0, ah1, ah2, ah3, bl0, bl1);
                mma16816(d[t], al0, al1, al2, al3, bh0, bh1);
            }
        }
#pragma unroll
        for (int t = 0; t < 4; t++) {
            float e0 = __expf(d[t][0]) * rz0;
            float e1 = __expf(d[t][1]) * rz0;
            float e2 = __expf(d[t][2]) * rz1;
            float e3 = __expf(d[t][3]) * rz1;
            int col = m0 + m0s + t * 8 + 2 * tg;
            float2 s01 = {e0, e1};
            float2 s23 = {e2, e3};
            *(float2*)&AMrow[(size_t)(j0s + gid) * NN + col] = s01;
            *(float2*)&AMrow[(size_t)(j0s + gid + 8) * NN + col] = s23;
            S.As[(j0s + gid) * 36 + (m0s >> 1) + t * 4 + tg] = bf16bits(e0) | (bf16bits(e1) << 16);
            S.As[(j0s + gid + 8) * 36 + (m0s >> 1) + t * 4 + tg] = bf16bits(e2) | (bf16bits(e3) << 16);
        }
        __syncthreads();
        // ---- o-stage: o += P @ v^T ----
#pragma unroll
        for (int kk = 0; kk < 4; kk++) {
            unsigned a[2][4];
#pragma unroll
            for (int jt = 0; jt < 2; jt++) {
                int r0 = wj * 32 + jt * 16;
                a[jt][0] = S.As[(r0 + gid) * 36 + kk * 8 + tg];
                a[jt][1] = S.As[(r0 + gid + 8) * 36 + kk * 8 + tg];
                a[jt][2] = S.As[(r0 + gid) * 36 + kk * 8 + tg + 4];
                a[jt][3] = S.As[(r0 + gid + 8) * 36 + kk * 8 + tg + 4];
            }
#pragma unroll
            for (int nt = 0; nt < 8; nt++) {
                unsigned b0 = S.Bs[(kk * 8 + tg) * 260 + wc * 64 + nt * 8 + gid];
                unsigned b1 = S.Bs[(kk * 8 + tg + 4) * 260 + wc * 64 + nt * 8 + gid];
                mma16816(acc[0][nt], a[0][0], a[0][1], a[0][2], a[0][3], b0, b1);
                mma16816(acc[1][nt], a[1][0], a[1][1], a[1][2], a[1][3], b0, b1);
            }
        }
        __syncthreads();
    }
    // ---- epilogue: smem transpose, out = x + gamma*o ----
    float gma = __ldg(gptr);
    float* fBs = (float*)S.Bs;
    for (int h = 0; h < 2; h++) {
        if (wj == h) {
#pragma unroll
            for (int jt = 0; jt < 2; jt++)
#pragma unroll
                for (int nt = 0; nt < 8; nt++) {
                    int rr = jt * 16 + gid;
                    int cc2 = wc * 64 + nt * 8 + tg * 2;
                    fBs[rr * 256 + cc2]           = acc[jt][nt][0];
                    fBs[rr * 256 + cc2 + 1]       = acc[jt][nt][1];
                    fBs[(rr + 8) * 256 + cc2]     = acc[jt][nt][2];
                    fBs[(rr + 8) * 256 + cc2 + 1] = acc[jt][nt][3];
                }
        }
        __syncthreads();
        int c = tid;
        const float* xrow = x + ((size_t)b * CC + c) * NN + j0 + h * 32;
        float* orow = outp + ((size_t)b * CC + c) * NN + j0 + h * 32;
#pragma unroll
        for (int jq = 0; jq < 8; jq++) {
            float4 o;
            o.x = fBs[(jq * 4 + 0) * 256 + c];
            o.y = fBs[(jq * 4 + 1) * 256 + c];
            o.z = fBs[(jq * 4 + 2) * 256 + c];
            o.w = fBs[(jq * 4 + 3) * 256 + c];
            float4 xr = *(const float4*)(xrow + jq * 4);
            float4 res = {xr.x + gma * o.x, xr.y + gma * o.y, xr.z + gma * o.z, xr.w + gma * o.w};
            *(float4*)(orow + jq * 4) = res;
        }
        __syncthreads();
    }
}

// ---------------- launch ----------------
extern "C" void kernel_launch(void* const* d_in, const int* in_sizes, int n_in,
                              void* d_out, int out_size) {
    const float* x  = (const float*)d_in[0];
    const float* Wq = (const float*)d_in[1];
    const float* bq = (const float*)d_in[2];
    const float* Wk = (const float*)d_in[3];
    const float* bk = (const float*)d_in[4];
    const float* Wv = (const float*)d_in[5];
    const float* bv = (const float*)d_in[6];
    const float* gm = (const float*)d_in[7];
    float* outp = (float*)d_out;
    float* AM = outp + (size_t)BN * CC * 64 * 64;

    // Unconditional (no static guard): idempotent, deterministic, capture-safe.
    cudaFuncSetAttribute(k_o2, cudaFuncAttributeMaxDynamicSharedMemorySize,
                         (int)sizeof(KoSmem));

    k_qk<<<dim3(32, BN), 256>>>(x, Wq, bq, Wk, bk);
    k_v<<<dim3(32, 4, BN), 256>>>(x, Wv, bv);
    k_z<<<dim3(64, BN), 256>>>();
    k_o2<<<dim3(64, BN), 256, sizeof(KoSmem)>>>(AM, x, gm, outp);
}

// round 5
// speedup vs baseline: 1.7430x; 1.4773x over previous
#include <cuda_runtime.h>
#include <cstdint>

#define BN 4
#define CC 256
#define NN 4096
#define CQ 32

// ---------------- scratch ----------------
__device__ unsigned g_qh[BN * NN * 16];         // [b][n][cw] hi bf16 pair (c even/odd packed)
__device__ unsigned g_ql[BN * NN * 16];         // lo residual
__device__ unsigned g_kh[BN * NN * 16];
__device__ unsigned g_kl[BN * NN * 16];
__device__ unsigned g_vtp[BN * CC * (NN / 2)]; // [b][c][m2] = pack(v[c][2m2], v[c][2m2+1])
__device__ float    g_rz[BN * NN];              // 1/Z per AM row j

__device__ __forceinline__ unsigned bf16bits(float f) {
    unsigned u = __float_as_uint(f);
    return (u + 0x7fffu + ((u >> 16) & 1u)) >> 16;
}

__device__ __forceinline__ unsigned sptr(const void* p) {
    unsigned a;
    asm("{ .reg .u64 t; cvta.to.shared.u64 t, %1; cvt.u32.u64 %0, t; }" : "=r"(a) : "l"(p));
    return a;
}

__device__ __forceinline__ void ldsm4(unsigned a, unsigned& r0, unsigned& r1, unsigned& r2, unsigned& r3) {
    asm volatile("ldmatrix.sync.aligned.m8n8.x4.shared.b16 {%0,%1,%2,%3}, [%4];"
                 : "=r"(r0), "=r"(r1), "=r"(r2), "=r"(r3) : "r"(a));
}

__device__ __forceinline__ void mma16816(float* d, unsigned a0, unsigned a1, unsigned a2, unsigned a3,
                                         unsigned b0, unsigned b1) {
    asm volatile(
        "mma.sync.aligned.m16n8k16.row.col.f32.bf16.bf16.f32 "
        "{%0,%1,%2,%3}, {%4,%5,%6,%7}, {%8,%9}, {%0,%1,%2,%3};\n"
        : "+f"(d[0]), "+f"(d[1]), "+f"(d[2]), "+f"(d[3])
        : "r"(a0), "r"(a1), "r"(a2), "r"(a3), "r"(b0), "r"(b1));
}

// ---------------- K1a: q,k = W{q,k} @ x + b, transposed + bf16 hi/lo split ----------------
__global__ void __launch_bounds__(256) k_qk(const float* __restrict__ x,
                                            const float* __restrict__ Wq, const float* __restrict__ bq,
                                            const float* __restrict__ Wk, const float* __restrict__ bk) {
    __shared__ float Ws[64][33];
    __shared__ float Xs[32][128];
    int b = blockIdx.y;
    int n0 = blockIdx.x * 128;
    int tid = threadIdx.x;
    const float* xb = x + (size_t)b * CC * NN;
    float acc[4][8];
#pragma unroll
    for (int i = 0; i < 4; i++)
#pragma unroll
        for (int j = 0; j < 8; j++) acc[i][j] = 0.f;
    int tr = tid >> 4, tn = tid & 15;
    for (int k0 = 0; k0 < CC; k0 += 32) {
        for (int i = tid; i < 64 * 32; i += 256) {
            int r = i >> 5, kk = i & 31;
            Ws[r][kk] = (r < 32) ? Wq[r * CC + k0 + kk] : Wk[(r - 32) * CC + k0 + kk];
        }
        for (int i = tid * 4; i < 32 * 128; i += 1024) {
            int kk = i >> 7, nn = i & 127;
            *(float4*)&Xs[kk][nn] = *(const float4*)&xb[(size_t)(k0 + kk) * NN + n0 + nn];
        }
        __syncthreads();
#pragma unroll
        for (int kk = 0; kk < 32; kk++) {
            float wf[4], xf[8];
#pragma unroll
            for (int i = 0; i < 4; i++) wf[i] = Ws[tr * 4 + i][kk];
            *(float4*)&xf[0] = *(float4*)&Xs[kk][tn * 8];
            *(float4*)&xf[4] = *(float4*)&Xs[kk][tn * 8 + 4];
#pragma unroll
            for (int i = 0; i < 4; i++)
#pragma unroll
                for (int j = 0; j < 8; j++) acc[i][j] += wf[i] * xf[j];
        }
        __syncthreads();
    }
#pragma unroll
    for (int i = 0; i < 4; i++) {
        int r = tr * 4 + i;
        float bias = (r < 32) ? bq[r] : bk[r - 32];
#pragma unroll
        for (int j = 0; j < 8; j++) acc[i][j] += bias;
    }
    unsigned hw[2][8], lw[2][8];
#pragma unroll
    for (int p = 0; p < 2; p++)
#pragma unroll
        for (int j = 0; j < 8; j++) {
            float a0 = acc[2 * p][j], a1 = acc[2 * p + 1][j];
            unsigned h0 = bf16bits(a0);
            unsigned h1 = bf16bits(a1);
            float f0 = __uint_as_float(h0 << 16);
            float f1 = __uint_as_float(h1 << 16);
            unsigned l0 = bf16bits(a0 - f0);
            unsigned l1 = bf16bits(a1 - f1);
            hw[p][j] = h0 | (h1 << 16);
            lw[p][j] = l0 | (l1 << 16);
        }
    unsigned* st = (unsigned*)&Xs[0][0];  // 128 x 17 staging
    bool isq = (tr < 8);
    int cw0 = (isq ? tr : tr - 8) * 2;
    for (int ph = 0; ph < 4; ph++) {
        bool mine = (ph < 2) ? isq : !isq;
        bool lo = (ph & 1);
        __syncthreads();
        if (mine) {
#pragma unroll
            for (int p = 0; p < 2; p++)
#pragma unroll
                for (int j = 0; j < 8; j++)
                    st[(tn * 8 + j) * 17 + cw0 + p] = lo ? lw[p][j] : hw[p][j];
        }
        __syncthreads();
        unsigned* dst = (ph == 0 ? g_qh : ph == 1 ? g_ql : ph == 2 ? g_kh : g_kl)
                        + ((size_t)b * NN + n0) * 16;
        int row = tid >> 1, w0 = (tid & 1) * 8;
        unsigned t0 = st[row * 17 + w0 + 0], t1 = st[row * 17 + w0 + 1];
        unsigned t2 = st[row * 17 + w0 + 2], t3 = st[row * 17 + w0 + 3];
        unsigned t4 = st[row * 17 + w0 + 4], t5 = st[row * 17 + w0 + 5];
        unsigned t6 = st[row * 17 + w0 + 6], t7 = st[row * 17 + w0 + 7];
        *(uint4*)&dst[row * 16 + w0] = make_uint4(t0, t1, t2, t3);
        *(uint4*)&dst[row * 16 + w0 + 4] = make_uint4(t4, t5, t6, t7);
    }
}

// ---------------- K1b: v = Wv @ x + bv, stored [c][m2] bf16-pair-packed (natural layout) ----------------
__global__ void __launch_bounds__(256) k_v(const float* __restrict__ x,
                                           const float* __restrict__ Wv, const float* __restrict__ bv) {
    __shared__ float Ws[64][33];
    __shared__ float Xs[32][128];
    int nb = blockIdx.x, cb = blockIdx.y, b = blockIdx.z;
    int n0 = nb * 128, c0 = cb * 64;
    int tid = threadIdx.x;
    const float* xb = x + (size_t)b * CC * NN;
    float acc[4][8];
#pragma unroll
    for (int i = 0; i < 4; i++)
#pragma unroll
        for (int j = 0; j < 8; j++) acc[i][j] = 0.f;
    int tr = tid >> 4, tn = tid & 15;
    for (int k0 = 0; k0 < CC; k0 += 32) {
        for (int i = tid; i < 64 * 32; i += 256) {
            int r = i >> 5, kk = i & 31;
            Ws[r][kk] = Wv[(size_t)(c0 + r) * CC + k0 + kk];
        }
        for (int i = tid * 4; i < 32 * 128; i += 1024) {
            int kk = i >> 7, nn = i & 127;
            *(float4*)&Xs[kk][nn] = *(const float4*)&xb[(size_t)(k0 + kk) * NN + n0 + nn];
        }
        __syncthreads();
#pragma unroll
        for (int kk = 0; kk < 32; kk++) {
            float wf[4], xf[8];
#pragma unroll
            for (int i = 0; i < 4; i++) wf[i] = Ws[tr * 4 + i][kk];
            *(float4*)&xf[0] = *(float4*)&Xs[kk][tn * 8];
            *(float4*)&xf[4] = *(float4*)&Xs[kk][tn * 8 + 4];
#pragma unroll
            for (int i = 0; i < 4; i++)
#pragma unroll
                for (int j = 0; j < 8; j++) acc[i][j] += wf[i] * xf[j];
        }
        __syncthreads();
    }
    // pack pairs along n, direct coalesced store (no transpose needed)
#pragma unroll
    for (int i = 0; i < 4; i++) {
        int c = c0 + tr * 4 + i;
        float bias = bv[c];
        unsigned w[4];
#pragma unroll
        for (int p = 0; p < 4; p++)
            w[p] = bf16bits(acc[i][2 * p] + bias) | (bf16bits(acc[i][2 * p + 1] + bias) << 16);
        *(uint4*)&g_vtp[((size_t)b * CC + c) * (NN / 2) + (n0 >> 1) + tn * 4] =
            make_uint4(w[0], w[1], w[2], w[3]);
    }
}

// ---------------- KZ: rz[j] = 1 / sum_i exp(s[i,j]), tensor-core S recompute, ldmatrix feeds ----------------
__global__ void __launch_bounds__(256) k_z() {
    __shared__ unsigned ksh[64 * 20], ksl[64 * 20];
    __shared__ unsigned qsh[64 * 20], qsl[64 * 20];
    __shared__ float zsh[64];
    int jb = blockIdx.x, b = blockIdx.y;
    int j0 = jb * 64;
    int tid = threadIdx.x;
    if (tid < 64) zsh[tid] = 0.f;
    {
        int r = tid >> 2, w = (tid & 3) * 4;
        *(uint4*)&ksh[r * 20 + w] = *(const uint4*)&g_kh[((size_t)b * NN + j0 + r) * 16 + w];
        *(uint4*)&ksl[r * 20 + w] = *(const uint4*)&g_kl[((size_t)b * NN + j0 + r) * 16 + w];
    }
    int warp = tid >> 5, lane = tid & 31, gid = lane >> 2, tg = lane & 3;
    int j0s = (warp & 3) * 16, m0s = (warp >> 2) * 32;
    // ldmatrix lane-address bases (bytes)
    unsigned aoff = ((j0s + (lane & 15)) * 20 + ((lane >> 4) << 2)) * 4;
    unsigned kshA = sptr(ksh) + aoff, kslA = sptr(ksl) + aoff;
    unsigned boff = (((lane & 7) + ((lane & 16) >> 1)) * 20 + ((lane & 8) >> 1)) * 4;
    unsigned qshB = sptr(qsh) + boff, qslB = sptr(qsl) + boff;
    float z0 = 0.f, z1 = 0.f;
    int lr = tid >> 2, lw = (tid & 3) * 4;
    for (int i0 = 0; i0 < NN; i0 += 64) {
        __syncthreads();
        *(uint4*)&qsh[lr * 20 + lw] = *(const uint4*)&g_qh[((size_t)b * NN + i0 + lr) * 16 + lw];
        *(uint4*)&qsl[lr * 20 + lw] = *(const uint4*)&g_ql[((size_t)b * NN + i0 + lr) * 16 + lw];
        __syncthreads();
        float d[4][4];
#pragma unroll
        for (int t = 0; t < 4; t++)
#pragma unroll
            for (int e = 0; e < 4; e++) d[t][e] = 0.f;
#pragma unroll
        for (int kk2 = 0; kk2 < 2; kk2++) {
            unsigned ah0, ah1, ah2, ah3, al0, al1, al2, al3;
            ldsm4(kshA + kk2 * 32, ah0, ah1, ah2, ah3);
            ldsm4(kslA + kk2 * 32, al0, al1, al2, al3);
#pragma unroll
            for (int tp = 0; tp < 4; tp += 2) {
                unsigned bh0, bh1, bh2, bh3, bl0, bl1, bl2, bl3;
                unsigned ro = (unsigned)((m0s + tp * 8) * 20 * 4);
                ldsm4(qshB + ro + kk2 * 32, bh0, bh1, bh2, bh3);
                ldsm4(qslB + ro + kk2 * 32, bl0, bl1, bl2, bl3);
                mma16816(d[tp], ah0, ah1, ah2, ah3, bh0, bh1);
                mma16816(d[tp], ah0, ah1, ah2, ah3, bl0, bl1);
                mma16816(d[tp], al0, al1, al2, al3, bh0, bh1);
                mma16816(d[tp + 1], ah0, ah1, ah2, ah3, bh2, bh3);
                mma16816(d[tp + 1], ah0, ah1, ah2, ah3, bl2, bl3);
                mma16816(d[tp + 1], al0, al1, al2, al3, bh2, bh3);
            }
        }
#pragma unroll
        for (int t = 0; t < 4; t++) {
            z0 += __expf(d[t][0]) + __expf(d[t][1]);
            z1 += __expf(d[t][2]) + __expf(d[t][3]);
        }
    }
    z0 += __shfl_xor_sync(0xffffffffu, z0, 1);
    z0 += __shfl_xor_sync(0xffffffffu, z0, 2);
    z1 += __shfl_xor_sync(0xffffffffu, z1, 1);
    z1 += __shfl_xor_sync(0xffffffffu, z1, 2);
    if (tg == 0) {
        atomicAdd(&zsh[j0s + gid], z0);
        atomicAdd(&zsh[j0s + gid + 8], z1);
    }
    __syncthreads();
    if (tid < 64) g_rz[(size_t)b * NN + j0 + tid] = 1.f / zsh[tid];
}

// ---------------- KO: fused S recompute + normalize + AM write + o = P @ v^T + residual ----------------
struct KoSmem {
    unsigned ksh[64 * 20];
    unsigned ksl[64 * 20];
    unsigned qsh[64 * 20];
    unsigned qsl[64 * 20];
    unsigned As[64 * 36];    // bf16 P tile
    unsigned Bs[256 * 36];   // v chunk [c][m2], ldmatrix-ready; reused as fp32 staging in epilogue
    float AMs[64 * 68];      // fp32 normalized P staging for coalesced AM store
    float rzs[64];
};

__global__ void __launch_bounds__(256) k_o2(float* __restrict__ AM, const float* __restrict__ x,
                                            const float* __restrict__ gptr, float* __restrict__ outp) {
    extern __shared__ KoSmem sm[];
    KoSmem& S = sm[0];
    int jb = blockIdx.x, b = blockIdx.y;
    int j0 = jb * 64;
    int tid = threadIdx.x;
    if (tid < 64) S.rzs[tid] = g_rz[(size_t)b * NN + j0 + tid];
    {
        int r = tid >> 2, w = (tid & 3) * 4;
        *(uint4*)&S.ksh[r * 20 + w] = *(const uint4*)&g_kh[((size_t)b * NN + j0 + r) * 16 + w];
        *(uint4*)&S.ksl[r * 20 + w] = *(const uint4*)&g_kl[((size_t)b * NN + j0 + r) * 16 + w];
    }
    __syncthreads();
    int warp = tid >> 5, lane = tid & 31, gid = lane >> 2, tg = lane & 3;
    int j0s = (warp & 3) * 16, m0s = (warp >> 2) * 32;
    float rz0 = S.rzs[j0s + gid], rz1 = S.rzs[j0s + gid + 8];
    int wj = warp >> 2, wc = warp & 3;
    // ldmatrix lane bases
    unsigned aoffS = ((j0s + (lane & 15)) * 20 + ((lane >> 4) << 2)) * 4;
    unsigned kshA = sptr(S.ksh) + aoffS, kslA = sptr(S.ksl) + aoffS;
    unsigned boffS = (((lane & 7) + ((lane & 16) >> 1)) * 20 + ((lane & 8) >> 1)) * 4;
    unsigned qshB = sptr(S.qsh) + boffS, qslB = sptr(S.qsl) + boffS;
    unsigned AsA = sptr(S.As) + (((lane & 15)) * 36 + ((lane >> 4) << 2)) * 4;
    unsigned BsB = sptr(S.Bs) + ((((lane & 7) + ((lane & 16) >> 1)) + wc * 64) * 36 + ((lane & 8) >> 1)) * 4;
    float acc[2][8][4];
#pragma unroll
    for (int a = 0; a < 2; a++)
#pragma unroll
        for (int n = 0; n < 8; n++)
#pragma unroll
            for (int c = 0; c < 4; c++) acc[a][n][c] = 0.f;
    float* AMrow = AM + ((size_t)b * NN + j0) * (size_t)NN;
    const unsigned* vb = g_vtp + (size_t)b * CC * (NN / 2);
    int lr = tid >> 2, lw = (tid & 3) * 4;
    int vr = tid >> 3, vch = (tid & 7) * 4;

    for (int m0 = 0; m0 < NN; m0 += 64) {
        // ---- loads: q chunk (64x16 words) + v chunk (256 rows x 32 words) ----
        *(uint4*)&S.qsh[lr * 20 + lw] = *(const uint4*)&g_qh[((size_t)b * NN + m0 + lr) * 16 + lw];
        *(uint4*)&S.qsl[lr * 20 + lw] = *(const uint4*)&g_ql[((size_t)b * NN + m0 + lr) * 16 + lw];
#pragma unroll
        for (int it = 0; it < 8; it++) {
            int row = it * 32 + vr;
            *(uint4*)&S.Bs[row * 36 + vch] =
                *(const uint4*)&vb[(size_t)row * (NN / 2) + (m0 >> 1) + vch];
        }
        __syncthreads();
        // ---- S-stage: tensor-core s, exp, normalize, stage AM + bf16 P ----
        float d[4][4];
#pragma unroll
        for (int t = 0; t < 4; t++)
#pragma unroll
            for (int e = 0; e < 4; e++) d[t][e] = 0.f;
#pragma unroll
        for (int kk2 = 0; kk2 < 2; kk2++) {
            unsigned ah0, ah1, ah2, ah3, al0, al1, al2, al3;
            ldsm4(kshA + kk2 * 32, ah0, ah1, ah2, ah3);
            ldsm4(kslA + kk2 * 32, al0, al1, al2, al3);
#pragma unroll
            for (int tp = 0; tp < 4; tp += 2) {
                unsigned bh0, bh1, bh2, bh3, bl0, bl1, bl2, bl3;
                unsigned ro = (unsigned)((m0s + tp * 8) * 20 * 4);
                ldsm4(qshB + ro + kk2 * 32, bh0, bh1, bh2, bh3);
                ldsm4(qslB + ro + kk2 * 32, bl0, bl1, bl2, bl3);
                mma16816(d[tp], ah0, ah1, ah2, ah3, bh0, bh1);
                mma16816(d[tp], ah0, ah1, ah2, ah3, bl0, bl1);
                mma16816(d[tp], al0, al1, al2, al3, bh0, bh1);
                mma16816(d[tp + 1], ah0, ah1, ah2, ah3, bh2, bh3);
                mma16816(d[tp + 1], ah0, ah1, ah2, ah3, bl2, bl3);
                mma16816(d[tp + 1], al0, al1, al2, al3, bh2, bh3);
            }
        }
#pragma unroll
        for (int t = 0; t < 4; t++) {
            float e0 = __expf(d[t][0]) * rz0;
            float e1 = __expf(d[t][1]) * rz0;
            float e2 = __expf(d[t][2]) * rz1;
            float e3 = __expf(d[t][3]) * rz1;
            int col = m0s + t * 8 + 2 * tg;
            *(float2*)&S.AMs[(j0s + gid) * 68 + col] = make_float2(e0, e1);
            *(float2*)&S.AMs[(j0s + gid + 8) * 68 + col] = make_float2(e2, e3);
            S.As[(j0s + gid) * 36 + (m0s >> 1) + t * 4 + tg] = bf16bits(e0) | (bf16bits(e1) << 16);
            S.As[(j0s + gid + 8) * 36 + (m0s >> 1) + t * 4 + tg] = bf16bits(e2) | (bf16bits(e3) << 16);
        }
        __syncthreads();
        // ---- coalesced AM store from staging ----
        {
            int row = tid >> 2, cg = (tid & 3) * 16;
            const float* src = &S.AMs[row * 68 + cg];
            float* dstp = AMrow + (size_t)row * NN + m0 + cg;
#pragma unroll
            for (int q = 0; q < 4; q++)
                *(float4*)(dstp + q * 4) = *(const float4*)(src + q * 4);
        }
        // ---- o-stage: o += P @ v^T (ldmatrix feeds) ----
#pragma unroll
        for (int kk = 0; kk < 4; kk++) {
            unsigned a0[4], a1[4];
            ldsm4(AsA + (unsigned)((wj * 32) * 36 * 4 + kk * 32), a0[0], a0[1], a0[2], a0[3]);
            ldsm4(AsA + (unsigned)((wj * 32 + 16) * 36 * 4 + kk * 32), a1[0], a1[1], a1[2], a1[3]);
#pragma unroll
            for (int ntp = 0; ntp < 4; ntp++) {
                unsigned b0a, b1a, b0b, b1b;
                ldsm4(BsB + (unsigned)((ntp * 16) * 36 * 4 + kk * 32), b0a, b1a, b0b, b1b);
                mma16816(acc[0][2 * ntp], a0[0], a0[1], a0[2], a0[3], b0a, b1a);
                mma16816(acc[1][2 * ntp], a1[0], a1[1], a1[2], a1[3], b0a, b1a);
                mma16816(acc[0][2 * ntp + 1], a0[0], a0[1], a0[2], a0[3], b0b, b1b);
                mma16816(acc[1][2 * ntp + 1], a1[0], a1[1], a1[2], a1[3], b0b, b1b);
            }
        }
        __syncthreads();
    }
    // ---- epilogue: smem transpose, out = x + gamma*o ----
    float gma = __ldg(gptr);
    float* fBs = (float*)S.Bs;
    for (int h = 0; h < 2; h++) {
        if (wj == h) {
#pragma unroll
            for (int jt = 0; jt < 2; jt++)
#pragma unroll
                for (int nt = 0; nt < 8; nt++) {
                    int rr = jt * 16 + gid;
                    int cc2 = wc * 64 + nt * 8 + tg * 2;
                    fBs[rr * 256 + cc2]           = acc[jt][nt][0];
                    fBs[rr * 256 + cc2 + 1]       = acc[jt][nt][1];
                    fBs[(rr + 8) * 256 + cc2]     = acc[jt][nt][2];
                    fBs[(rr + 8) * 256 + cc2 + 1] = acc[jt][nt][3];
                }
        }
        __syncthreads();
        int c = tid;
        const float* xrow = x + ((size_t)b * CC + c) * NN + j0 + h * 32;
        float* orow = outp + ((size_t)b * CC + c) * NN + j0 + h * 32;
#pragma unroll
        for (int jq = 0; jq < 8; jq++) {
            float4 o;
            o.x = fBs[(jq * 4 + 0) * 256 + c];
            o.y = fBs[(jq * 4 + 1) * 256 + c];
            o.z = fBs[(jq * 4 + 2) * 256 + c];
            o.w = fBs[(jq * 4 + 3) * 256 + c];
            float4 xr = *(const float4*)(xrow + jq * 4);
            float4 res = {xr.x + gma * o.x, xr.y + gma * o.y, xr.z + gma * o.z, xr.w + gma * o.w};
            *(float4*)(orow + jq * 4) = res;
        }
        __syncthreads();
    }
}

// ---------------- launch ----------------
extern "C" void kernel_launch(void* const* d_in, const int* in_sizes, int n_in,
                              void* d_out, int out_size) {
    const float* x  = (const float*)d_in[0];
    const float* Wq = (const float*)d_in[1];
    const float* bq = (const float*)d_in[2];
    const float* Wk = (const float*)d_in[3];
    const float* bk = (const float*)d_in[4];
    const float* Wv = (const float*)d_in[5];
    const float* bv = (const float*)d_in[6];
    const float* gm = (const float*)d_in[7];
    float* outp = (float*)d_out;
    float* AM = outp + (size_t)BN * CC * 64 * 64;

    cudaFuncSetAttribute(k_o2, cudaFuncAttributeMaxDynamicSharedMemorySize,
                         (int)sizeof(KoSmem));

    k_qk<<<dim3(32, BN), 256>>>(x, Wq, bq, Wk, bk);
    k_v<<<dim3(32, 4, BN), 256>>>(x, Wv, bv);
    k_z<<<dim3(64, BN), 256>>>();
    k_o2<<<dim3(64, BN), 256, sizeof(KoSmem)>>>(AM, x, gm, outp);
}

// round 7
// speedup vs baseline: 1.9540x; 1.1210x over previous
#include <cuda_runtime.h>
#include <cstdint>

#define BN 4
#define CC 256
#define NN 4096

// ---------------- scratch ----------------
__device__ unsigned g_qh[BN * NN * 16];         // [b][n][cw] hi bf16 pair (c even/odd packed)
__device__ unsigned g_ql[BN * NN * 16];         // lo residual
__device__ unsigned g_kh[BN * NN * 16];
__device__ unsigned g_kl[BN * NN * 16];
__device__ unsigned g_vtp[BN * CC * (NN / 2)]; // [b][c][m2] = pack(v[c][2m2], v[c][2m2+1])
__device__ float    g_rz[BN * NN];              // 1/Z per AM row j

__device__ __forceinline__ unsigned bf16bits(float f) {
    unsigned u = __float_as_uint(f);
    return (u + 0x7fffu + ((u >> 16) & 1u)) >> 16;
}

__device__ __forceinline__ unsigned sptr(const void* p) {
    unsigned a;
    asm("{ .reg .u64 t; cvta.to.shared.u64 t, %1; cvt.u32.u64 %0, t; }" : "=r"(a) : "l"(p));
    return a;
}

__device__ __forceinline__ void ldsm4(unsigned a, unsigned& r0, unsigned& r1, unsigned& r2, unsigned& r3) {
    asm volatile("ldmatrix.sync.aligned.m8n8.x4.shared.b16 {%0,%1,%2,%3}, [%4];"
                 : "=r"(r0), "=r"(r1), "=r"(r2), "=r"(r3) : "r"(a));
}

__device__ __forceinline__ void mma16816(float* d, unsigned a0, unsigned a1, unsigned a2, unsigned a3,
                                         unsigned b0, unsigned b1) {
    asm volatile(
        "mma.sync.aligned.m16n8k16.row.col.f32.bf16.bf16.f32 "
        "{%0,%1,%2,%3}, {%4,%5,%6,%7}, {%8,%9}, {%0,%1,%2,%3};\n"
        : "+f"(d[0]), "+f"(d[1]), "+f"(d[2]), "+f"(d[3])
        : "r"(a0), "r"(a1), "r"(a2), "r"(a3), "r"(b0), "r"(b1));
}

__device__ __forceinline__ void cpa16(unsigned dst, const void* src) {
    asm volatile("cp.async.cg.shared.global [%0], [%1], 16;" :: "r"(dst), "l"(src));
}

// ---------------- K1a: q,k = W{q,k} @ x + b, transposed + bf16 hi/lo split ----------------
__global__ void __launch_bounds__(256) k_qk(const float* __restrict__ x,
                                            const float* __restrict__ Wq, const float* __restrict__ bq,
                                            const float* __restrict__ Wk, const float* __restrict__ bk) {
    __shared__ float Ws[64][33];
    __shared__ float Xs[32][128];
    int b = blockIdx.y;
    int n0 = blockIdx.x * 128;
    int tid = threadIdx.x;
    const float* xb = x + (size_t)b * CC * NN;
    float acc[4][8];
#pragma unroll
    for (int i = 0; i < 4; i++)
#pragma unroll
        for (int j = 0; j < 8; j++) acc[i][j] = 0.f;
    int tr = tid >> 4, tn = tid & 15;
    for (int k0 = 0; k0 < CC; k0 += 32) {
        for (int i = tid; i < 64 * 32; i += 256) {
            int r = i >> 5, kk = i & 31;
            Ws[r][kk] = (r < 32) ? Wq[r * CC + k0 + kk] : Wk[(r - 32) * CC + k0 + kk];
        }
        for (int i = tid * 4; i < 32 * 128; i += 1024) {
            int kk = i >> 7, nn = i & 127;
            *(float4*)&Xs[kk][nn] = *(const float4*)&xb[(size_t)(k0 + kk) * NN + n0 + nn];
        }
        __syncthreads();
#pragma unroll
        for (int kk = 0; kk < 32; kk++) {
            float wf[4], xf[8];
#pragma unroll
            for (int i = 0; i < 4; i++) wf[i] = Ws[tr * 4 + i][kk];
            *(float4*)&xf[0] = *(float4*)&Xs[kk][tn * 8];
            *(float4*)&xf[4] = *(float4*)&Xs[kk][tn * 8 + 4];
#pragma unroll
            for (int i = 0; i < 4; i++)
#pragma unroll
                for (int j = 0; j < 8; j++) acc[i][j] += wf[i] * xf[j];
        }
        __syncthreads();
    }
#pragma unroll
    for (int i = 0; i < 4; i++) {
        int r = tr * 4 + i;
        float bias = (r < 32) ? bq[r] : bk[r - 32];
#pragma unroll
        for (int j = 0; j < 8; j++) acc[i][j] += bias;
    }
    unsigned hw[2][8], lw[2][8];
#pragma unroll
    for (int p = 0; p < 2; p++)
#pragma unroll
        for (int j = 0; j < 8; j++) {
            float a0 = acc[2 * p][j], a1 = acc[2 * p + 1][j];
            unsigned h0 = bf16bits(a0);
            unsigned h1 = bf16bits(a1);
            float f0 = __uint_as_float(h0 << 16);
            float f1 = __uint_as_float(h1 << 16);
            unsigned l0 = bf16bits(a0 - f0);
            unsigned l1 = bf16bits(a1 - f1);
            hw[p][j] = h0 | (h1 << 16);
            lw[p][j] = l0 | (l1 << 16);
        }
    unsigned* st = (unsigned*)&Xs[0][0];  // 128 x 17 staging
    bool isq = (tr < 8);
    int cw0 = (isq ? tr : tr - 8) * 2;
    for (int ph = 0; ph < 4; ph++) {
        bool mine = (ph < 2) ? isq : !isq;
        bool lo = (ph & 1);
        __syncthreads();
        if (mine) {
#pragma unroll
            for (int p = 0; p < 2; p++)
#pragma unroll
                for (int j = 0; j < 8; j++)
                    st[(tn * 8 + j) * 17 + cw0 + p] = lo ? lw[p][j] : hw[p][j];
        }
        __syncthreads();
        unsigned* dst = (ph == 0 ? g_qh : ph == 1 ? g_ql : ph == 2 ? g_kh : g_kl)
                        + ((size_t)b * NN + n0) * 16;
        int row = tid >> 1, w0 = (tid & 1) * 8;
        unsigned t0 = st[row * 17 + w0 + 0], t1 = st[row * 17 + w0 + 1];
        unsigned t2 = st[row * 17 + w0 + 2], t3 = st[row * 17 + w0 + 3];
        unsigned t4 = st[row * 17 + w0 + 4], t5 = st[row * 17 + w0 + 5];
        unsigned t6 = st[row * 17 + w0 + 6], t7 = st[row * 17 + w0 + 7];
        *(uint4*)&dst[row * 16 + w0] = make_uint4(t0, t1, t2, t3);
        *(uint4*)&dst[row * 16 + w0 + 4] = make_uint4(t4, t5, t6, t7);
    }
}

// ---------------- K1b: v = Wv @ x + bv, stored [c][m2] bf16-pair-packed ----------------
__global__ void __launch_bounds__(256) k_v(const float* __restrict__ x,
                                           const float* __restrict__ Wv, const float* __restrict__ bv) {
    __shared__ float Ws[64][33];
    __shared__ float Xs[32][128];
    int nb = blockIdx.x, cb = blockIdx.y, b = blockIdx.z;
    int n0 = nb * 128, c0 = cb * 64;
    int tid = threadIdx.x;
    const float* xb = x + (size_t)b * CC * NN;
    float acc[4][8];
#pragma unroll
    for (int i = 0; i < 4; i++)
#pragma unroll
        for (int j = 0; j < 8; j++) acc[i][j] = 0.f;
    int tr = tid >> 4, tn = tid & 15;
    for (int k0 = 0; k0 < CC; k0 += 32) {
        for (int i = tid; i < 64 * 32; i += 256) {
            int r = i >> 5, kk = i & 31;
            Ws[r][kk] = Wv[(size_t)(c0 + r) * CC + k0 + kk];
        }
        for (int i = tid * 4; i < 32 * 128; i += 1024) {
            int kk = i >> 7, nn = i & 127;
            *(float4*)&Xs[kk][nn] = *(const float4*)&xb[(size_t)(k0 + kk) * NN + n0 + nn];
        }
        __syncthreads();
#pragma unroll
        for (int kk = 0; kk < 32; kk++) {
            float wf[4], xf[8];
#pragma unroll
            for (int i = 0; i < 4; i++) wf[i] = Ws[tr * 4 + i][kk];
            *(float4*)&xf[0] = *(float4*)&Xs[kk][tn * 8];
            *(float4*)&xf[4] = *(float4*)&Xs[kk][tn * 8 + 4];
#pragma unroll
            for (int i = 0; i < 4; i++)
#pragma unroll
                for (int j = 0; j < 8; j++) acc[i][j] += wf[i] * xf[j];
        }
        __syncthreads();
    }
#pragma unroll
    for (int i = 0; i < 4; i++) {
        int c = c0 + tr * 4 + i;
        float bias = bv[c];
        unsigned w[4];
#pragma unroll
        for (int p = 0; p < 4; p++)
            w[p] = bf16bits(acc[i][2 * p] + bias) | (bf16bits(acc[i][2 * p + 1] + bias) << 16);
        *(uint4*)&g_vtp[((size_t)b * CC + c) * (NN / 2) + (n0 >> 1) + tn * 4] =
            make_uint4(w[0], w[1], w[2], w[3]);
    }
}

// ---------------- KZ: rz[j] = 1 / sum_i exp(s[i,j]) ----------------
__global__ void __launch_bounds__(256) k_z() {
    __shared__ unsigned ksh[64 * 20], ksl[64 * 20];
    __shared__ unsigned qsh[64 * 20], qsl[64 * 20];
    __shared__ float zsh[64];
    int jb = blockIdx.x, b = blockIdx.y;
    int j0 = jb * 64;
    int tid = threadIdx.x;
    if (tid < 64) zsh[tid] = 0.f;
    {
        int r = tid >> 2, w = (tid & 3) * 4;
        *(uint4*)&ksh[r * 20 + w] = *(const uint4*)&g_kh[((size_t)b * NN + j0 + r) * 16 + w];
        *(uint4*)&ksl[r * 20 + w] = *(const uint4*)&g_kl[((size_t)b * NN + j0 + r) * 16 + w];
    }
    int warp = tid >> 5, lane = tid & 31, gid = lane >> 2, tg = lane & 3;
    int j0s = (warp & 3) * 16, m0s = (warp >> 2) * 32;
    unsigned aoff = ((j0s + (lane & 15)) * 20 + ((lane >> 4) << 2)) * 4;
    unsigned kshA = sptr(ksh) + aoff, kslA = sptr(ksl) + aoff;
    unsigned boff = (((lane & 7) + ((lane & 16) >> 1)) * 20 + ((lane & 8) >> 1)) * 4;
    unsigned qshB = sptr(qsh) + boff, qslB = sptr(qsl) + boff;
    float z0 = 0.f, z1 = 0.f;
    int lr = tid >> 2, lw = (tid & 3) * 4;
    for (int i0 = 0; i0 < NN; i0 += 64) {
        __syncthreads();
        *(uint4*)&qsh[lr * 20 + lw] = *(const uint4*)&g_qh[((size_t)b * NN + i0 + lr) * 16 + lw];
        *(uint4*)&qsl[lr * 20 + lw] = *(const uint4*)&g_ql[((size_t)b * NN + i0 + lr) * 16 + lw];
        __syncthreads();
        float d[4][4];
#pragma unroll
        for (int t = 0; t < 4; t++)
#pragma unroll
            for (int e = 0; e < 4; e++) d[t][e] = 0.f;
#pragma unroll
        for (int kk2 = 0; kk2 < 2; kk2++) {
            unsigned ah0, ah1, ah2, ah3, al0, al1, al2, al3;
            ldsm4(kshA + kk2 * 32, ah0, ah1, ah2, ah3);
            ldsm4(kslA + kk2 * 32, al0, al1, al2, al3);
#pragma unroll
            for (int tp = 0; tp < 4; tp += 2) {
                unsigned bh0, bh1, bh2, bh3, bl0, bl1, bl2, bl3;
                unsigned ro = (unsigned)((m0s + tp * 8) * 20 * 4);
                ldsm4(qshB + ro + kk2 * 32, bh0, bh1, bh2, bh3);
                ldsm4(qslB + ro + kk2 * 32, bl0, bl1, bl2, bl3);
                mma16816(d[tp], ah0, ah1, ah2, ah3, bh0, bh1);
                mma16816(d[tp], ah0, ah1, ah2, ah3, bl0, bl1);
                mma16816(d[tp], al0, al1, al2, al3, bh0, bh1);
                mma16816(d[tp + 1], ah0, ah1, ah2, ah3, bh2, bh3);
                mma16816(d[tp + 1], ah0, ah1, ah2, ah3, bl2, bl3);
                mma16816(d[tp + 1], al0, al1, al2, al3, bh2, bh3);
            }
        }
#pragma unroll
        for (int t = 0; t < 4; t++) {
            z0 += __expf(d[t][0]) + __expf(d[t][1]);
            z1 += __expf(d[t][2]) + __expf(d[t][3]);
        }
    }
    z0 += __shfl_xor_sync(0xffffffffu, z0, 1);
    z0 += __shfl_xor_sync(0xffffffffu, z0, 2);
    z1 += __shfl_xor_sync(0xffffffffu, z1, 1);
    z1 += __shfl_xor_sync(0xffffffffu, z1, 2);
    if (tg == 0) {
        atomicAdd(&zsh[j0s + gid], z0);
        atomicAdd(&zsh[j0s + gid + 8], z1);
    }
    __syncthreads();
    if (tid < 64) g_rz[(size_t)b * NN + j0 + tid] = 1.f / zsh[tid];
}

// ---------------- KO4: 128-j tile, 512 thr, cp.async double-buffered ----------------
struct Ko4Smem {
    unsigned ksh[128 * 20];
    unsigned ksl[128 * 20];
    unsigned qsh[2][64 * 20];
    unsigned qsl[2][64 * 20];
    unsigned As[128 * 36];     // bf16 P tile
    unsigned Bs[2][256 * 36];  // v chunks (double buffered); reused fp32 in epilogue
    float AMs[128 * 68];       // normalized P staging for coalesced AM store
    float rzs[128];
};
#define QBUF_B (64 * 20 * 4)
#define VBUF_B (256 * 36 * 4)

__global__ void __launch_bounds__(512) k_o4(float* __restrict__ AM, const float* __restrict__ x,
                                            const float* __restrict__ gptr, float* __restrict__ outp) {
    extern __shared__ Ko4Smem s4[];
    Ko4Smem& S = s4[0];
    int jb = blockIdx.x, b = blockIdx.y;
    int j0 = jb * 128;
    int tid = threadIdx.x;
    if (tid < 128) S.rzs[tid] = g_rz[(size_t)b * NN + j0 + tid];
    // K tiles once: 2 bufs x 128 rows x 4 uint4 = 1024 / 512 = 2 per thread
    for (int u = tid; u < 1024; u += 512) {
        int bufl = u >> 9, r = (u >> 2) & 127, w = (u & 3) * 4;
        const unsigned* src = (bufl ? g_kl : g_kh) + ((size_t)b * NN + j0 + r) * 16 + w;
        unsigned* dst = (bufl ? S.ksl : S.ksh) + r * 20 + w;
        *(uint4*)dst = *(const uint4*)src;
    }
    unsigned qshS = sptr(S.qsh[0]), qslS = sptr(S.qsl[0]), BsS = sptr(S.Bs[0]);
    const unsigned* vbp = g_vtp + (size_t)b * CC * (NN / 2);
    // q-load role: 1 uint4/thread; v-load role: 4 uint4/thread
    int qlf = tid >> 8, qlr = (tid >> 2) & 63, qlw = (tid & 3) * 4;
    // prologue: async-load tile 0 into buf 0
    {
        const unsigned* qs = (qlf ? g_ql : g_qh) + ((size_t)b * NN + 0 + qlr) * 16 + qlw;
        cpa16((qlf ? qslS : qshS) + (qlr * 20 + qlw) * 4, qs);
#pragma unroll
        for (int it = 0; it < 4; it++) {
            int idx = it * 512 + tid;
            int r = idx >> 3, ch = (idx & 7) * 4;
            cpa16(BsS + (r * 36 + ch) * 4, vbp + (size_t)r * (NN / 2) + 0 + ch);
        }
    }
    asm volatile("cp.async.commit_group;");
    __syncthreads();

    int warp = tid >> 5, lane = tid & 31, gid = lane >> 2, tg = lane & 3;
    int j0s = (warp & 7) * 16, m0s = (warp >> 3) * 32;   // S-stage roles (16 warps)
    float rz0 = S.rzs[j0s + gid], rz1 = S.rzs[j0s + gid + 8];
    int wj = warp >> 2, wc = warp & 3;                   // O-stage roles
    unsigned aoffS = ((j0s + (lane & 15)) * 20 + ((lane >> 4) << 2)) * 4;
    unsigned kshA = sptr(S.ksh) + aoffS, kslA = sptr(S.ksl) + aoffS;
    unsigned boffS = (((lane & 7) + ((lane & 16) >> 1)) * 20 + ((lane & 8) >> 1)) * 4;
    unsigned AsA = sptr(S.As) + ((lane & 15) * 36 + ((lane >> 4) << 2)) * 4;
    unsigned boffO = ((((lane & 7) + ((lane & 16) >> 1)) + wc * 64) * 36 + ((lane & 8) >> 1)) * 4;
    float acc[2][8][4];
#pragma unroll
    for (int a = 0; a < 2; a++)
#pragma unroll
        for (int n = 0; n < 8; n++)
#pragma unroll
            for (int c = 0; c < 4; c++) acc[a][n][c] = 0.f;
    float* AMrow = AM + ((size_t)b * NN + j0) * (size_t)NN;

    for (int t = 0; t < 64; t++) {
        int bb = t & 1;
        int m0 = t * 64;
        // async-prefetch tile t+1 into buf bb^1
        if (t + 1 < 64) {
            int m1 = m0 + 64;
            const unsigned* qs = (qlf ? g_ql : g_qh) + ((size_t)b * NN + m1 + qlr) * 16 + qlw;
            cpa16((qlf ? qslS : qshS) + (bb ^ 1) * QBUF_B + (qlr * 20 + qlw) * 4, qs);
#pragma unroll
            for (int it = 0; it < 4; it++) {
                int idx = it * 512 + tid;
                int r = idx >> 3, ch = (idx & 7) * 4;
                cpa16(BsS + (bb ^ 1) * VBUF_B + (r * 36 + ch) * 4,
                      vbp + (size_t)r * (NN / 2) + (m1 >> 1) + ch);
            }
        }
        asm volatile("cp.async.commit_group;");
        asm volatile("cp.async.wait_group 1;");
        __syncthreads();
        // ---- S-stage ----
        unsigned qshB = qshS + bb * QBUF_B + boffS;
        unsigned qslB = qslS + bb * QBUF_B + boffS;
        float d[4][4];
#pragma unroll
        for (int tt = 0; tt < 4; tt++)
#pragma unroll
            for (int e = 0; e < 4; e++) d[tt][e] = 0.f;
#pragma unroll
        for (int kk2 = 0; kk2 < 2; kk2++) {
            unsigned ah0, ah1, ah2, ah3, al0, al1, al2, al3;
            ldsm4(kshA + kk2 * 32, ah0, ah1, ah2, ah3);
            ldsm4(kslA + kk2 * 32, al0, al1, al2, al3);
#pragma unroll
            for (int tp = 0; tp < 4; tp += 2) {
                unsigned bh0, bh1, bh2, bh3, bl0, bl1, bl2, bl3;
                unsigned ro = (unsigned)((m0s + tp * 8) * 20 * 4);
                ldsm4(qshB + ro + kk2 * 32, bh0, bh1, bh2, bh3);
                ldsm4(qslB + ro + kk2 * 32, bl0, bl1, bl2, bl3);
                mma16816(d[tp], ah0, ah1, ah2, ah3, bh0, bh1);
                mma16816(d[tp], ah0, ah1, ah2, ah3, bl0, bl1);
                mma16816(d[tp], al0, al1, al2, al3, bh0, bh1);
                mma16816(d[tp + 1], ah0, ah1, ah2, ah3, bh2, bh3);
                mma16816(d[tp + 1], ah0, ah1, ah2, ah3, bl2, bl3);
                mma16816(d[tp + 1], al0, al1, al2, al3, bh2, bh3);
            }
        }
#pragma unroll
        for (int tt = 0; tt < 4; tt++) {
            float e0 = __expf(d[tt][0]) * rz0;
            float e1 = __expf(d[tt][1]) * rz0;
            float e2 = __expf(d[tt][2]) * rz1;
            float e3 = __expf(d[tt][3]) * rz1;
            int col = m0s + tt * 8 + 2 * tg;
            *(float2*)&S.AMs[(j0s + gid) * 68 + col] = make_float2(e0, e1);
            *(float2*)&S.AMs[(j0s + gid + 8) * 68 + col] = make_float2(e2, e3);
            S.As[(j0s + gid) * 36 + (m0s >> 1) + tt * 4 + tg] = bf16bits(e0) | (bf16bits(e1) << 16);
            S.As[(j0s + gid + 8) * 36 + (m0s >> 1) + tt * 4 + tg] = bf16bits(e2) | (bf16bits(e3) << 16);
        }
        __syncthreads();
        // ---- coalesced AM store (128 rows x 16 float4 = 2048 / 512 = 4 each) ----
        for (int u = tid; u < 2048; u += 512) {
            int r = u >> 4, g4 = u & 15;
            *(float4*)&AMrow[(size_t)r * NN + m0 + g4 * 4] = *(float4*)&S.AMs[r * 68 + g4 * 4];
        }
        // ---- O-stage: o += P @ v^T ----
        unsigned BsB = BsS + bb * VBUF_B + boffO;
#pragma unroll
        for (int kk = 0; kk < 4; kk++) {
            unsigned a0[4], a1[4];
            ldsm4(AsA + (unsigned)((wj * 32) * 144 + kk * 32), a0[0], a0[1], a0[2], a0[3]);
            ldsm4(AsA + (unsigned)((wj * 32 + 16) * 144 + kk * 32), a1[0], a1[1], a1[2], a1[3]);
#pragma unroll
            for (int ntp = 0; ntp < 4; ntp++) {
                unsigned b0a, b1a, b0b, b1b;
                ldsm4(BsB + (unsigned)((ntp * 16) * 144 + kk * 32), b0a, b1a, b0b, b1b);
                mma16816(acc[0][2 * ntp], a0[0], a0[1], a0[2], a0[3], b0a, b1a);
                mma16816(acc[1][2 * ntp], a1[0], a1[1], a1[2], a1[3], b0a, b1a);
                mma16816(acc[0][2 * ntp + 1], a0[0], a0[1], a0[2], a0[3], b0b, b1b);
                mma16816(acc[1][2 * ntp + 1], a1[0], a1[1], a1[2], a1[3], b0b, b1b);
            }
        }
        __syncthreads();
    }
    // ---- epilogue: 4 phases of 32 j rows; smem transpose, out = x + gamma*o ----
    float gma = __ldg(gptr);
    float* fBs = (float*)S.Bs[0];  // 32 x 256 fp32
    int ec = tid & 255, ejh = tid >> 8;
    for (int h = 0; h < 4; h++) {
        if (wj == h) {
#pragma unroll
            for (int jt = 0; jt < 2; jt++)
#pragma unroll
                for (int nt = 0; nt < 8; nt++) {
                    int rr = jt * 16 + gid;
                    int cc2 = wc * 64 + nt * 8 + tg * 2;
                    fBs[rr * 256 + cc2]           = acc[jt][nt][0];
                    fBs[rr * 256 + cc2 + 1]       = acc[jt][nt][1];
                    fBs[(rr + 8) * 256 + cc2]     = acc[jt][nt][2];
                    fBs[(rr + 8) * 256 + cc2 + 1] = acc[jt][nt][3];
                }
        }
        __syncthreads();
        const float* xrow = x + ((size_t)b * CC + ec) * NN + j0 + h * 32 + ejh * 16;
        float* orow = outp + ((size_t)b * CC + ec) * NN + j0 + h * 32 + ejh * 16;
#pragma unroll
        for (int jq = 0; jq < 4; jq++) {
            float4 o;
            o.x = fBs[(ejh * 16 + jq * 4 + 0) * 256 + ec];
            o.y = fBs[(ejh * 16 + jq * 4 + 1) * 256 + ec];
            o.z = fBs[(ejh * 16 + jq * 4 + 2) * 256 + ec];
            o.w = fBs[(ejh * 16 + jq * 4 + 3) * 256 + ec];
            float4 xr = *(const float4*)(xrow + jq * 4);
            float4 res = {xr.x + gma * o.x, xr.y + gma * o.y, xr.z + gma * o.z, xr.w + gma * o.w};
            *(float4*)(orow + jq * 4) = res;
        }
        __syncthreads();
    }
}

// ---------------- launch ----------------
extern "C" void kernel_launch(void* const* d_in, const int* in_sizes, int n_in,
                              void* d_out, int out_size) {
    const float* x  = (const float*)d_in[0];
    const float* Wq = (const float*)d_in[1];
    const float* bq = (const float*)d_in[2];
    const float* Wk = (const float*)d_in[3];
    const float* bk = (const float*)d_in[4];
    const float* Wv = (const float*)d_in[5];
    const float* bv = (const float*)d_in[6];
    const float* gm = (const float*)d_in[7];
    float* outp = (float*)d_out;
    float* AM = outp + (size_t)BN * CC * 64 * 64;

    cudaFuncSetAttribute(k_o4, cudaFuncAttributeMaxDynamicSharedMemorySize,
                         (int)sizeof(Ko4Smem));

    k_qk<<<dim3(32, BN), 256>>>(x, Wq, bq, Wk, bk);
    k_v<<<dim3(32, 4, BN), 256>>>(x, Wv, bv);
    k_z<<<dim3(64, BN), 256>>>();
    k_o4<<<dim3(32, BN), 512, sizeof(Ko4Smem)>>>(AM, x, gm, outp);
}

// round 8
// speedup vs baseline: 2.1084x; 1.0791x over previous
#include <cuda_runtime.h>
#include <cstdint>

#define BN 4
#define CC 256
#define NN 4096
#define LOG2E 1.4426950408889634f

// ---------------- scratch ----------------
__device__ unsigned g_qh[BN * NN * 16];         // [b][n][cw] hi bf16 pair (c even/odd packed)
__device__ unsigned g_ql[BN * NN * 16];         // lo residual
__device__ unsigned g_kh[BN * NN * 16];         // k pre-scaled by log2(e)
__device__ unsigned g_kl[BN * NN * 16];
__device__ unsigned g_vtp[BN * CC * (NN / 2)]; // [b][c][m2] = pack(v[c][2m2], v[c][2m2+1])

__device__ __forceinline__ unsigned bf16bits(float f) {
    unsigned u = __float_as_uint(f);
    return (u + 0x7fffu + ((u >> 16) & 1u)) >> 16;
}

__device__ __forceinline__ unsigned sptr(const void* p) {
    unsigned a;
    asm("{ .reg .u64 t; cvta.to.shared.u64 t, %1; cvt.u32.u64 %0, t; }" : "=r"(a) : "l"(p));
    return a;
}

__device__ __forceinline__ float ex2f(float x) {
    float y;
    asm("ex2.approx.f32 %0, %1;" : "=f"(y) : "f"(x));
    return y;
}

__device__ __forceinline__ void ldsm4(unsigned a, unsigned& r0, unsigned& r1, unsigned& r2, unsigned& r3) {
    asm volatile("ldmatrix.sync.aligned.m8n8.x4.shared.b16 {%0,%1,%2,%3}, [%4];"
                 : "=r"(r0), "=r"(r1), "=r"(r2), "=r"(r3) : "r"(a));
}

__device__ __forceinline__ void mma16816(float* d, unsigned a0, unsigned a1, unsigned a2, unsigned a3,
                                         unsigned b0, unsigned b1) {
    asm volatile(
        "mma.sync.aligned.m16n8k16.row.col.f32.bf16.bf16.f32 "
        "{%0,%1,%2,%3}, {%4,%5,%6,%7}, {%8,%9}, {%0,%1,%2,%3};\n"
        : "+f"(d[0]), "+f"(d[1]), "+f"(d[2]), "+f"(d[3])
        : "r"(a0), "r"(a1), "r"(a2), "r"(a3), "r"(b0), "r"(b1));
}

__device__ __forceinline__ void cpa16(unsigned dst, const void* src) {
    asm volatile("cp.async.cg.shared.global [%0], [%1], 16;" :: "r"(dst), "l"(src));
}

// ---------------- K1a: q,k projections; k scaled by log2e; transposed + bf16 hi/lo split ----------------
__global__ void __launch_bounds__(256) k_qk(const float* __restrict__ x,
                                            const float* __restrict__ Wq, const float* __restrict__ bq,
                                            const float* __restrict__ Wk, const float* __restrict__ bk) {
    __shared__ float Ws[64][33];
    __shared__ float Xs[32][128];
    int b = blockIdx.y;
    int n0 = blockIdx.x * 128;
    int tid = threadIdx.x;
    const float* xb = x + (size_t)b * CC * NN;
    float acc[4][8];
#pragma unroll
    for (int i = 0; i < 4; i++)
#pragma unroll
        for (int j = 0; j < 8; j++) acc[i][j] = 0.f;
    int tr = tid >> 4, tn = tid & 15;
    for (int k0 = 0; k0 < CC; k0 += 32) {
        for (int i = tid; i < 64 * 32; i += 256) {
            int r = i >> 5, kk = i & 31;
            Ws[r][kk] = (r < 32) ? Wq[r * CC + k0 + kk] : Wk[(r - 32) * CC + k0 + kk];
        }
        for (int i = tid * 4; i < 32 * 128; i += 1024) {
            int kk = i >> 7, nn = i & 127;
            *(float4*)&Xs[kk][nn] = *(const float4*)&xb[(size_t)(k0 + kk) * NN + n0 + nn];
        }
        __syncthreads();
#pragma unroll
        for (int kk = 0; kk < 32; kk++) {
            float wf[4], xf[8];
#pragma unroll
            for (int i = 0; i < 4; i++) wf[i] = Ws[tr * 4 + i][kk];
            *(float4*)&xf[0] = *(float4*)&Xs[kk][tn * 8];
            *(float4*)&xf[4] = *(float4*)&Xs[kk][tn * 8 + 4];
#pragma unroll
            for (int i = 0; i < 4; i++)
#pragma unroll
                for (int j = 0; j < 8; j++) acc[i][j] += wf[i] * xf[j];
        }
        __syncthreads();
    }
#pragma unroll
    for (int i = 0; i < 4; i++) {
        int r = tr * 4 + i;
        float bias = (r < 32) ? bq[r] : bk[r - 32];
        float scale = (r < 32) ? 1.f : LOG2E;  // fold log2e into k so exp(s) = ex2(s')
#pragma unroll
        for (int j = 0; j < 8; j++) acc[i][j] = (acc[i][j] + bias) * scale;
    }
    unsigned hw[2][8], lw[2][8];
#pragma unroll
    for (int p = 0; p < 2; p++)
#pragma unroll
        for (int j = 0; j < 8; j++) {
            float a0 = acc[2 * p][j], a1 = acc[2 * p + 1][j];
            unsigned h0 = bf16bits(a0);
            unsigned h1 = bf16bits(a1);
            float f0 = __uint_as_float(h0 << 16);
            float f1 = __uint_as_float(h1 << 16);
            unsigned l0 = bf16bits(a0 - f0);
            unsigned l1 = bf16bits(a1 - f1);
            hw[p][j] = h0 | (h1 << 16);
            lw[p][j] = l0 | (l1 << 16);
        }
    unsigned* st = (unsigned*)&Xs[0][0];  // 128 x 17 staging
    bool isq = (tr < 8);
    int cw0 = (isq ? tr : tr - 8) * 2;
    for (int ph = 0; ph < 4; ph++) {
        bool mine = (ph < 2) ? isq : !isq;
        bool lo = (ph & 1);
        __syncthreads();
        if (mine) {
#pragma unroll
            for (int p = 0; p < 2; p++)
#pragma unroll
                for (int j = 0; j < 8; j++)
                    st[(tn * 8 + j) * 17 + cw0 + p] = lo ? lw[p][j] : hw[p][j];
        }
        __syncthreads();
        unsigned* dst = (ph == 0 ? g_qh : ph == 1 ? g_ql : ph == 2 ? g_kh : g_kl)
                        + ((size_t)b * NN + n0) * 16;
        int row = tid >> 1, w0 = (tid & 1) * 8;
        unsigned t0 = st[row * 17 + w0 + 0], t1 = st[row * 17 + w0 + 1];
        unsigned t2 = st[row * 17 + w0 + 2], t3 = st[row * 17 + w0 + 3];
        unsigned t4 = st[row * 17 + w0 + 4], t5 = st[row * 17 + w0 + 5];
        unsigned t6 = st[row * 17 + w0 + 6], t7 = st[row * 17 + w0 + 7];
        *(uint4*)&dst[row * 16 + w0] = make_uint4(t0, t1, t2, t3);
        *(uint4*)&dst[row * 16 + w0 + 4] = make_uint4(t4, t5, t6, t7);
    }
}

// ---------------- K1b: v = Wv @ x + bv, stored [c][m2] bf16-pair-packed ----------------
__global__ void __launch_bounds__(256) k_v(const float* __restrict__ x,
                                           const float* __restrict__ Wv, const float* __restrict__ bv) {
    __shared__ float Ws[64][33];
    __shared__ float Xs[32][128];
    int nb = blockIdx.x, cb = blockIdx.y, b = blockIdx.z;
    int n0 = nb * 128, c0 = cb * 64;
    int tid = threadIdx.x;
    const float* xb = x + (size_t)b * CC * NN;
    float acc[4][8];
#pragma unroll
    for (int i = 0; i < 4; i++)
#pragma unroll
        for (int j = 0; j < 8; j++) acc[i][j] = 0.f;
    int tr = tid >> 4, tn = tid & 15;
    for (int k0 = 0; k0 < CC; k0 += 32) {
        for (int i = tid; i < 64 * 32; i += 256) {
            int r = i >> 5, kk = i & 31;
            Ws[r][kk] = Wv[(size_t)(c0 + r) * CC + k0 + kk];
        }
        for (int i = tid * 4; i < 32 * 128; i += 1024) {
            int kk = i >> 7, nn = i & 127;
            *(float4*)&Xs[kk][nn] = *(const float4*)&xb[(size_t)(k0 + kk) * NN + n0 + nn];
        }
        __syncthreads();
#pragma unroll
        for (int kk = 0; kk < 32; kk++) {
            float wf[4], xf[8];
#pragma unroll
            for (int i = 0; i < 4; i++) wf[i] = Ws[tr * 4 + i][kk];
            *(float4*)&xf[0] = *(float4*)&Xs[kk][tn * 8];
            *(float4*)&xf[4] = *(float4*)&Xs[kk][tn * 8 + 4];
#pragma unroll
            for (int i = 0; i < 4; i++)
#pragma unroll
                for (int j = 0; j < 8; j++) acc[i][j] += wf[i] * xf[j];
        }
        __syncthreads();
    }
#pragma unroll
    for (int i = 0; i < 4; i++) {
        int c = c0 + tr * 4 + i;
        float bias = bv[c];
        unsigned w[4];
#pragma unroll
        for (int p = 0; p < 4; p++)
            w[p] = bf16bits(acc[i][2 * p] + bias) | (bf16bits(acc[i][2 * p + 1] + bias) << 16);
        *(uint4*)&g_vtp[((size_t)b * CC + c) * (NN / 2) + (n0 >> 1) + tn * 4] =
            make_uint4(w[0], w[1], w[2], w[3]);
    }
}

// ---------------- KO5: fused Z sweep (phase A) + pipelined S/O sweep (phase B) ----------------
struct Ko5Smem {
    unsigned ksh[128 * 20];
    unsigned ksl[128 * 20];
    unsigned qsh[2][64 * 20];
    unsigned qsl[2][64 * 20];
    unsigned As[128 * 36];     // bf16 P tile (single buffer; protected by 2 bars/iter)
    unsigned Bs[2][256 * 36];  // v chunks; phase-A q buffers; epilogue fp32 staging
    float AMs[128 * 68];       // normalized P staging
    float zsh[128];
};
#define QBUF_B (64 * 20 * 4)
#define VBUF_B (256 * 36 * 4)
#define PA_BUF (2 * 128 * 20 * 4)
#define PA_HL  (128 * 20 * 4)

__global__ void __launch_bounds__(512) k_o5(float* __restrict__ AM, const float* __restrict__ x,
                                            const float* __restrict__ gptr, float* __restrict__ outp) {
    extern __shared__ Ko5Smem s5[];
    Ko5Smem& S = s5[0];
    int jb = blockIdx.x, b = blockIdx.y;
    int j0 = jb * 128;
    int tid = threadIdx.x;
    if (tid < 128) S.zsh[tid] = 0.f;
    // K tiles once
    for (int u = tid; u < 1024; u += 512) {
        int bufl = u >> 9, r = (u >> 2) & 127, w = (u & 3) * 4;
        const unsigned* src = (bufl ? g_kl : g_kh) + ((size_t)b * NN + j0 + r) * 16 + w;
        unsigned* dst = (bufl ? S.ksl : S.ksh) + r * 20 + w;
        *(uint4*)dst = *(const uint4*)src;
    }
    __syncthreads();

    int warp = tid >> 5, lane = tid & 31, gid = lane >> 2, tg = lane & 3;
    int j0s = (warp & 7) * 16;
    int m0sB = (warp >> 3) * 32, m0sA = (warp >> 3) * 64;
    int wj = warp >> 2, wc = warp & 3;
    unsigned aoffS = ((j0s + (lane & 15)) * 20 + ((lane >> 4) << 2)) * 4;
    unsigned kshA = sptr(S.ksh) + aoffS, kslA = sptr(S.ksl) + aoffS;
    unsigned boffS = (((lane & 7) + ((lane & 16) >> 1)) * 20 + ((lane & 8) >> 1)) * 4;
    unsigned AsA = sptr(S.As) + ((lane & 15) * 36 + ((lane >> 4) << 2)) * 4;
    unsigned boffO = ((((lane & 7) + ((lane & 16) >> 1)) + wc * 64) * 36 + ((lane & 8) >> 1)) * 4;
    unsigned qshS = sptr(S.qsh[0]), qslS = sptr(S.qsl[0]), BsS = sptr(S.Bs[0]);
    const unsigned* vbp = g_vtp + (size_t)b * CC * (NN / 2);

    // hoisted k A-fragments (loop-invariant across BOTH phases)
    unsigned ah2[2][4], al2[2][4];
    ldsm4(kshA + 0, ah2[0][0], ah2[0][1], ah2[0][2], ah2[0][3]);
    ldsm4(kshA + 32, ah2[1][0], ah2[1][1], ah2[1][2], ah2[1][3]);
    ldsm4(kslA + 0, al2[0][0], al2[0][1], al2[0][2], al2[0][3]);
    ldsm4(kslA + 32, al2[1][0], al2[1][1], al2[1][2], al2[1][3]);

    // ================= phase A: Z sweep (q streamed in 128-row chunks into Bs region) ================
    {
        for (int u = tid; u < 1024; u += 512) {
            int hl = u >> 9, r = (u >> 2) & 127, w4 = (u & 3) * 4;
            cpa16(BsS + hl * PA_HL + (r * 20 + w4) * 4,
                  (hl ? g_ql : g_qh) + ((size_t)b * NN + r) * 16 + w4);
        }
        asm volatile("cp.async.commit_group;");
    }
    float z0 = 0.f, z1 = 0.f;
    for (int it = 0; it < 32; it++) {
        if (it < 31) {
            int i0n = (it + 1) * 128;
            for (int u = tid; u < 1024; u += 512) {
                int hl = u >> 9, r = (u >> 2) & 127, w4 = (u & 3) * 4;
                cpa16(BsS + ((it + 1) & 1) * PA_BUF + hl * PA_HL + (r * 20 + w4) * 4,
                      (hl ? g_ql : g_qh) + ((size_t)b * NN + i0n + r) * 16 + w4);
            }
        }
        asm volatile("cp.async.commit_group;");
        asm volatile("cp.async.wait_group 1;");
        __syncthreads();
        unsigned qh_b = BsS + (it & 1) * PA_BUF + boffS;
        unsigned ql_b = qh_b + PA_HL;
#pragma unroll
        for (int tp = 0; tp < 8; tp += 2) {
            float d2[2][4];
#pragma unroll
            for (int a = 0; a < 2; a++)
#pragma unroll
                for (int e = 0; e < 4; e++) d2[a][e] = 0.f;
#pragma unroll
            for (int kk2 = 0; kk2 < 2; kk2++) {
                unsigned ro = (unsigned)((m0sA + tp * 8) * 80) + kk2 * 32;
                unsigned bh0, bh1, bh2, bh3, bl0, bl1, bl2, bl3;
                ldsm4(qh_b + ro, bh0, bh1, bh2, bh3);
                ldsm4(ql_b + ro, bl0, bl1, bl2, bl3);
                mma16816(d2[0], ah2[kk2][0], ah2[kk2][1], ah2[kk2][2], ah2[kk2][3], bh0, bh1);
                mma16816(d2[0], ah2[kk2][0], ah2[kk2][1], ah2[kk2][2], ah2[kk2][3], bl0, bl1);
                mma16816(d2[0], al2[kk2][0], al2[kk2][1], al2[kk2][2], al2[kk2][3], bh0, bh1);
                mma16816(d2[1], ah2[kk2][0], ah2[kk2][1], ah2[kk2][2], ah2[kk2][3], bh2, bh3);
                mma16816(d2[1], ah2[kk2][0], ah2[kk2][1], ah2[kk2][2], ah2[kk2][3], bl2, bl3);
                mma16816(d2[1], al2[kk2][0], al2[kk2][1], al2[kk2][2], al2[kk2][3], bh2, bh3);
            }
            z0 += ex2f(d2[0][0]) + ex2f(d2[0][1]) + ex2f(d2[1][0]) + ex2f(d2[1][1]);
            z1 += ex2f(d2[0][2]) + ex2f(d2[0][3]) + ex2f(d2[1][2]) + ex2f(d2[1][3]);
        }
    }
    z0 += __shfl_xor_sync(0xffffffffu, z0, 1);
    z0 += __shfl_xor_sync(0xffffffffu, z0, 2);
    z1 += __shfl_xor_sync(0xffffffffu, z1, 1);
    z1 += __shfl_xor_sync(0xffffffffu, z1, 2);
    if (tg == 0) {
        atomicAdd(&S.zsh[j0s + gid], z0);
        atomicAdd(&S.zsh[j0s + gid + 8], z1);
    }
    asm volatile("cp.async.wait_group 0;");
    __syncthreads();
    float rz0 = 1.f / S.zsh[j0s + gid], rz1 = 1.f / S.zsh[j0s + gid + 8];

    // ================= phase B: pipelined S(t) + O(t-1) ================
    float acc[2][8][4];
#pragma unroll
    for (int a = 0; a < 2; a++)
#pragma unroll
        for (int n = 0; n < 8; n++)
#pragma unroll
            for (int c = 0; c < 4; c++) acc[a][n][c] = 0.f;
    float* AMrow = AM + ((size_t)b * NN + j0) * (size_t)NN;
    int qlf = tid >> 8, qlr = (tid >> 2) & 63, qlw = (tid & 3) * 4;
    {  // prologue: q(0)
        cpa16((qlf ? qslS : qshS) + (qlr * 20 + qlw) * 4,
              (qlf ? g_ql : g_qh) + ((size_t)b * NN + qlr) * 16 + qlw);
        asm volatile("cp.async.commit_group;");
    }
    for (int t = 0; t < 64; t++) {
        int bb = t & 1;
        int m0 = t * 64;
        if (t < 63) {
            const unsigned* qs = (qlf ? g_ql : g_qh) + ((size_t)b * NN + (m0 + 64) + qlr) * 16 + qlw;
            cpa16((qlf ? qslS : qshS) + (bb ^ 1) * QBUF_B + (qlr * 20 + qlw) * 4, qs);
        }
#pragma unroll
        for (int itv = 0; itv < 4; itv++) {
            int idx = itv * 512 + tid;
            int r = idx >> 3, ch = (idx & 7) * 4;
            cpa16(BsS + bb * VBUF_B + (r * 36 + ch) * 4,
                  vbp + (size_t)r * (NN / 2) + (m0 >> 1) + ch);
        }
        asm volatile("cp.async.commit_group;");
        asm volatile("cp.async.wait_group 1;");
        __syncthreads();  // barA
        // ---- S-mma(t) ----
        unsigned qshB = qshS + bb * QBUF_B + boffS;
        unsigned qslB = qslS + bb * QBUF_B + boffS;
        float d[4][4];
#pragma unroll
        for (int tt = 0; tt < 4; tt++)
#pragma unroll
            for (int e = 0; e < 4; e++) d[tt][e] = 0.f;
#pragma unroll
        for (int kk2 = 0; kk2 < 2; kk2++) {
#pragma unroll
            for (int tp = 0; tp < 4; tp += 2) {
                unsigned ro = (unsigned)((m0sB + tp * 8) * 80) + kk2 * 32;
                unsigned bh0, bh1, bh2, bh3, bl0, bl1, bl2, bl3;
                ldsm4(qshB + ro, bh0, bh1, bh2, bh3);
                ldsm4(qslB + ro, bl0, bl1, bl2, bl3);
                mma16816(d[tp], ah2[kk2][0], ah2[kk2][1], ah2[kk2][2], ah2[kk2][3], bh0, bh1);
                mma16816(d[tp], ah2[kk2][0], ah2[kk2][1], ah2[kk2][2], ah2[kk2][3], bl0, bl1);
                mma16816(d[tp], al2[kk2][0], al2[kk2][1], al2[kk2][2], al2[kk2][3], bh0, bh1);
                mma16816(d[tp + 1], ah2[kk2][0], ah2[kk2][1], ah2[kk2][2], ah2[kk2][3], bh2, bh3);
                mma16816(d[tp + 1], ah2[kk2][0], ah2[kk2][1], ah2[kk2][2], ah2[kk2][3], bl2, bl3);
                mma16816(d[tp + 1], al2[kk2][0], al2[kk2][1], al2[kk2][2], al2[kk2][3], bh2, bh3);
            }
        }
        // ---- O-mma(t-1) + AM store(t-1): hides the d-latency, fills tensor pipe ----
        if (t > 0) {
            unsigned BsB = BsS + (bb ^ 1) * VBUF_B + boffO;
#pragma unroll
            for (int kk = 0; kk < 4; kk++) {
                unsigned a0[4], a1[4];
                ldsm4(AsA + (unsigned)((wj * 32) * 144 + kk * 32), a0[0], a0[1], a0[2], a0[3]);
                ldsm4(AsA + (unsigned)((wj * 32 + 16) * 144 + kk * 32), a1[0], a1[1], a1[2], a1[3]);
#pragma unroll
                for (int ntp = 0; ntp < 4; ntp++) {
                    unsigned b0a, b1a, b0b, b1b;
                    ldsm4(BsB + (unsigned)((ntp * 16) * 144 + kk * 32), b0a, b1a, b0b, b1b);
                    mma16816(acc[0][2 * ntp], a0[0], a0[1], a0[2], a0[3], b0a, b1a);
                    mma16816(acc[1][2 * ntp], a1[0], a1[1], a1[2], a1[3], b0a, b1a);
                    mma16816(acc[0][2 * ntp + 1], a0[0], a0[1], a0[2], a0[3], b0b, b1b);
                    mma16816(acc[1][2 * ntp + 1], a1[0], a1[1], a1[2], a1[3], b0b, b1b);
                }
            }
            int m0p = m0 - 64;
            for (int u = tid; u < 2048; u += 512) {
                int r = u >> 4, g4 = u & 15;
                *(float4*)&AMrow[(size_t)r * NN + m0p + g4 * 4] = *(float4*)&S.AMs[r * 68 + g4 * 4];
            }
        }
        __syncthreads();  // barB
        // ---- exp + normalize + stage ----
#pragma unroll
        for (int tt = 0; tt < 4; tt++) {
            float e0 = ex2f(d[tt][0]) * rz0;
            float e1 = ex2f(d[tt][1]) * rz0;
            float e2 = ex2f(d[tt][2]) * rz1;
            float e3 = ex2f(d[tt][3]) * rz1;
            int col = m0sB + tt * 8 + 2 * tg;
            *(float2*)&S.AMs[(j0s + gid) * 68 + col] = make_float2(e0, e1);
            *(float2*)&S.AMs[(j0s + gid + 8) * 68 + col] = make_float2(e2, e3);
            S.As[(j0s + gid) * 36 + (m0sB >> 1) + tt * 4 + tg] = bf16bits(e0) | (bf16bits(e1) << 16);
            S.As[(j0s + gid + 8) * 36 + (m0sB >> 1) + tt * 4 + tg] = bf16bits(e2) | (bf16bits(e3) << 16);
        }
    }
    // ---- drain: O(63) + AM(63) ----
    asm volatile("cp.async.wait_group 0;");
    __syncthreads();
    {
        unsigned BsB = BsS + 1 * VBUF_B + boffO;
#pragma unroll
        for (int kk = 0; kk < 4; kk++) {
            unsigned a0[4], a1[4];
            ldsm4(AsA + (unsigned)((wj * 32) * 144 + kk * 32), a0[0], a0[1], a0[2], a0[3]);
            ldsm4(AsA + (unsigned)((wj * 32 + 16) * 144 + kk * 32), a1[0], a1[1], a1[2], a1[3]);
#pragma unroll
            for (int ntp = 0; ntp < 4; ntp++) {
                unsigned b0a, b1a, b0b, b1b;
                ldsm4(BsB + (unsigned)((ntp * 16) * 144 + kk * 32), b0a, b1a, b0b, b1b);
                mma16816(acc[0][2 * ntp], a0[0], a0[1], a0[2], a0[3], b0a, b1a);
                mma16816(acc[1][2 * ntp], a1[0], a1[1], a1[2], a1[3], b0a, b1a);
                mma16816(acc[0][2 * ntp + 1], a0[0], a0[1], a0[2], a0[3], b0b, b1b);
                mma16816(acc[1][2 * ntp + 1], a1[0], a1[1], a1[2], a1[3], b0b, b1b);
            }
        }
        for (int u = tid; u < 2048; u += 512) {
            int r = u >> 4, g4 = u & 15;
            *(float4*)&AMrow[(size_t)r * NN + 4032 + g4 * 4] = *(float4*)&S.AMs[r * 68 + g4 * 4];
        }
    }
    __syncthreads();
    // ---- epilogue: out = x + gamma*o ----
    float gma = __ldg(gptr);
    float* fBs = (float*)S.Bs[0];  // 32 x 256 fp32
    int ec = tid & 255, ejh = tid >> 8;
    for (int h = 0; h < 4; h++) {
        if (wj == h) {
#pragma unroll
            for (int jt = 0; jt < 2; jt++)
#pragma unroll
                for (int nt = 0; nt < 8; nt++) {
                    int rr = jt * 16 + gid;
                    int cc2 = wc * 64 + nt * 8 + tg * 2;
                    fBs[rr * 256 + cc2]           = acc[jt][nt][0];
                    fBs[rr * 256 + cc2 + 1]       = acc[jt][nt][1];
                    fBs[(rr + 8) * 256 + cc2]     = acc[jt][nt][2];
                    fBs[(rr + 8) * 256 + cc2 + 1] = acc[jt][nt][3];
                }
        }
        __syncthreads();
        const float* xrow = x + ((size_t)b * CC + ec) * NN + j0 + h * 32 + ejh * 16;
        float* orow = outp + ((size_t)b * CC + ec) * NN + j0 + h * 32 + ejh * 16;
#pragma unroll
        for (int jq = 0; jq < 4; jq++) {
            float4 o;
            o.x = fBs[(ejh * 16 + jq * 4 + 0) * 256 + ec];
            o.y = fBs[(ejh * 16 + jq * 4 + 1) * 256 + ec];
            o.z = fBs[(ejh * 16 + jq * 4 + 2) * 256 + ec];
            o.w = fBs[(ejh * 16 + jq * 4 + 3) * 256 + ec];
            float4 xr = *(const float4*)(xrow + jq * 4);
            float4 res = {xr.x + gma * o.x, xr.y + gma * o.y, xr.z + gma * o.z, xr.w + gma * o.w};
            *(float4*)(orow + jq * 4) = res;
        }
        __syncthreads();
    }
}

// ---------------- launch ----------------
extern "C" void kernel_launch(void* const* d_in, const int* in_sizes, int n_in,
                              void* d_out, int out_size) {
    const float* x  = (const float*)d_in[0];
    const float* Wq = (const float*)d_in[1];
    const float* bq = (const float*)d_in[2];
    const float* Wk = (const float*)d_in[3];
    const float* bk = (const float*)d_in[4];
    const float* Wv = (const float*)d_in[5];
    const float* bv = (const float*)d_in[6];
    const float* gm = (const float*)d_in[7];
    float* outp = (float*)d_out;
    float* AM = outp + (size_t)BN * CC * 64 * 64;

    cudaFuncSetAttribute(k_o5, cudaFuncAttributeMaxDynamicSharedMemorySize,
                         (int)sizeof(Ko5Smem));

    k_qk<<<dim3(32, BN), 256>>>(x, Wq, bq, Wk, bk);
    k_v<<<dim3(32, 4, BN), 256>>>(x, Wv, bv);
    k_o5<<<dim3(32, BN), 512, sizeof(Ko5Smem)>>>(AM, x, gm, outp);
}

// round 9
// speedup vs baseline: 2.2631x; 1.0733x over previous
#include <cuda_runtime.h>
#include <cstdint>

#define BN 4
#define CC 256
#define NN 4096
#define LOG2E 1.4426950408889634f

// ---------------- scratch ----------------
__device__ unsigned g_qh[BN * NN * 16];         // [b][n][cw] hi bf16 pair (c even/odd packed)
__device__ unsigned g_ql[BN * NN * 16];         // lo residual
__device__ unsigned g_kh[BN * NN * 16];         // k pre-scaled by log2(e)
__device__ unsigned g_kl[BN * NN * 16];
__device__ unsigned g_vtp[BN * CC * (NN / 2)]; // [b][c][m2] = pack(v[c][2m2], v[c][2m2+1])

__device__ __forceinline__ unsigned bf16bits(float f) {
    unsigned u = __float_as_uint(f);
    return (u + 0x7fffu + ((u >> 16) & 1u)) >> 16;
}

__device__ __forceinline__ unsigned sptr(const void* p) {
    unsigned a;
    asm("{ .reg .u64 t; cvta.to.shared.u64 t, %1; cvt.u32.u64 %0, t; }" : "=r"(a) : "l"(p));
    return a;
}

__device__ __forceinline__ float ex2f(float x) {
    float y;
    asm("ex2.approx.f32 %0, %1;" : "=f"(y) : "f"(x));
    return y;
}

__device__ __forceinline__ void ldsm4(unsigned a, unsigned& r0, unsigned& r1, unsigned& r2, unsigned& r3) {
    asm volatile("ldmatrix.sync.aligned.m8n8.x4.shared.b16 {%0,%1,%2,%3}, [%4];"
                 : "=r"(r0), "=r"(r1), "=r"(r2), "=r"(r3) : "r"(a));
}

__device__ __forceinline__ void mma16816(float* d, unsigned a0, unsigned a1, unsigned a2, unsigned a3,
                                         unsigned b0, unsigned b1) {
    asm volatile(
        "mma.sync.aligned.m16n8k16.row.col.f32.bf16.bf16.f32 "
        "{%0,%1,%2,%3}, {%4,%5,%6,%7}, {%8,%9}, {%0,%1,%2,%3};\n"
        : "+f"(d[0]), "+f"(d[1]), "+f"(d[2]), "+f"(d[3])
        : "r"(a0), "r"(a1), "r"(a2), "r"(a3), "r"(b0), "r"(b1));
}

__device__ __forceinline__ void cpa16(unsigned dst, const void* src) {
    asm volatile("cp.async.cg.shared.global [%0], [%1], 16;" :: "r"(dst), "l"(src));
}

// ---------------- K1a: q,k projections; 64-n tile, 256 CTAs for latency hiding ----------------
__global__ void __launch_bounds__(256) k_qk(const float* __restrict__ x,
                                            const float* __restrict__ Wq, const float* __restrict__ bq,
                                            const float* __restrict__ Wk, const float* __restrict__ bk) {
    __shared__ float Ws[64][33];
    __shared__ float Xs[32][68];
    int b = blockIdx.y;
    int n0 = blockIdx.x * 64;
    int tid = threadIdx.x;
    const float* xb = x + (size_t)b * CC * NN;
    float acc[4][4];
#pragma unroll
    for (int i = 0; i < 4; i++)
#pragma unroll
        for (int j = 0; j < 4; j++) acc[i][j] = 0.f;
    int tr = tid >> 4, tn = tid & 15;
    for (int k0 = 0; k0 < CC; k0 += 32) {
        for (int i = tid; i < 64 * 32; i += 256) {
            int r = i >> 5, kk = i & 31;
            Ws[r][kk] = (r < 32) ? Wq[r * CC + k0 + kk] : Wk[(r - 32) * CC + k0 + kk];
        }
        {
            int kk = tid >> 3, nn = (tid & 7) * 8;
            *(float4*)&Xs[kk][nn] = *(const float4*)&xb[(size_t)(k0 + kk) * NN + n0 + nn];
            *(float4*)&Xs[kk][nn + 4] = *(const float4*)&xb[(size_t)(k0 + kk) * NN + n0 + nn + 4];
        }
        __syncthreads();
#pragma unroll
        for (int kk = 0; kk < 32; kk++) {
            float wf[4], xf[4];
#pragma unroll
            for (int i = 0; i < 4; i++) wf[i] = Ws[tr * 4 + i][kk];
            *(float4*)&xf[0] = *(float4*)&Xs[kk][tn * 4];
#pragma unroll
            for (int i = 0; i < 4; i++)
#pragma unroll
                for (int j = 0; j < 4; j++) acc[i][j] += wf[i] * xf[j];
        }
        __syncthreads();
    }
#pragma unroll
    for (int i = 0; i < 4; i++) {
        int r = tr * 4 + i;
        float bias = (r < 32) ? bq[r] : bk[r - 32];
        float scale = (r < 32) ? 1.f : LOG2E;  // fold log2e into k so exp(s) = ex2(s')
#pragma unroll
        for (int j = 0; j < 4; j++) acc[i][j] = (acc[i][j] + bias) * scale;
    }
    unsigned hw[2][4], lw[2][4];
#pragma unroll
    for (int p = 0; p < 2; p++)
#pragma unroll
        for (int j = 0; j < 4; j++) {
            float a0 = acc[2 * p][j], a1 = acc[2 * p + 1][j];
            unsigned h0 = bf16bits(a0);
            unsigned h1 = bf16bits(a1);
            float f0 = __uint_as_float(h0 << 16);
            float f1 = __uint_as_float(h1 << 16);
            unsigned l0 = bf16bits(a0 - f0);
            unsigned l1 = bf16bits(a1 - f1);
            hw[p][j] = h0 | (h1 << 16);
            lw[p][j] = l0 | (l1 << 16);
        }
    unsigned* st = (unsigned*)&Xs[0][0];  // 64 x 17 staging
    bool isq = (tr < 8);
    int cw0 = (isq ? tr : tr - 8) * 2;
    for (int ph = 0; ph < 4; ph++) {
        bool mine = (ph < 2) ? isq : !isq;
        bool lo = (ph & 1);
        __syncthreads();
        if (mine) {
#pragma unroll
            for (int p = 0; p < 2; p++)
#pragma unroll
                for (int j = 0; j < 4; j++)
                    st[(tn * 4 + j) * 17 + cw0 + p] = lo ? lw[p][j] : hw[p][j];
        }
        __syncthreads();
        unsigned* dst = (ph == 0 ? g_qh : ph == 1 ? g_ql : ph == 2 ? g_kh : g_kl)
                        + ((size_t)b * NN + n0) * 16;
        int row = tid >> 2, w0 = (tid & 3) * 4;
        unsigned t0 = st[row * 17 + w0 + 0], t1 = st[row * 17 + w0 + 1];
        unsigned t2 = st[row * 17 + w0 + 2], t3 = st[row * 17 + w0 + 3];
        *(uint4*)&dst[row * 16 + w0] = make_uint4(t0, t1, t2, t3);
    }
}

// ---------------- K1b: v projection; full 256-c column per CTA (x read ONCE) ----------------
__global__ void __launch_bounds__(256) k_v(const float* __restrict__ x,
                                           const float* __restrict__ Wv, const float* __restrict__ bv) {
    __shared__ float Ws[256][33];
    __shared__ float Xs[32][36];
    int nb = blockIdx.x, b = blockIdx.y;
    int n0 = nb * 32;
    int tid = threadIdx.x;
    const float* xb = x + (size_t)b * CC * NN;
    float acc[8][4];
#pragma unroll
    for (int i = 0; i < 8; i++)
#pragma unroll
        for (int j = 0; j < 4; j++) acc[i][j] = 0.f;
    int tr = tid >> 3, tc = tid & 7;  // 8 c-rows x 4 n-cols per thread
    for (int k0 = 0; k0 < CC; k0 += 32) {
        // Wv chunk: 256 rows x 32 k (each thread: one row, 32 words via 8 float4 global reads)
        {
            const float4* src = (const float4*)&Wv[(size_t)tid * CC + k0];
#pragma unroll
            for (int q = 0; q < 8; q++) {
                float4 w4 = src[q];
                Ws[tid][q * 4 + 0] = w4.x;
                Ws[tid][q * 4 + 1] = w4.y;
                Ws[tid][q * 4 + 2] = w4.z;
                Ws[tid][q * 4 + 3] = w4.w;
            }
        }
        // x chunk: 32 k x 32 n
        {
            int kk = tid >> 3, nn = (tid & 7) * 4;
            *(float4*)&Xs[kk][nn] = *(const float4*)&xb[(size_t)(k0 + kk) * NN + n0 + nn];
        }
        __syncthreads();
#pragma unroll
        for (int kk = 0; kk < 32; kk++) {
            float xf[4];
            *(float4*)&xf[0] = *(float4*)&Xs[kk][tc * 4];
#pragma unroll
            for (int i = 0; i < 8; i++) {
                float wv = Ws[tr * 8 + i][kk];
#pragma unroll
                for (int j = 0; j < 4; j++) acc[i][j] += wv * xf[j];
            }
        }
        __syncthreads();
    }
#pragma unroll
    for (int i = 0; i < 8; i++) {
        int c = tr * 8 + i;
        float bias = bv[c];
        unsigned w0 = bf16bits(acc[i][0] + bias) | (bf16bits(acc[i][1] + bias) << 16);
        unsigned w1 = bf16bits(acc[i][2] + bias) | (bf16bits(acc[i][3] + bias) << 16);
        *(uint2*)&g_vtp[((size_t)b * CC + c) * (NN / 2) + (n0 >> 1) + tc * 2] = make_uint2(w0, w1);
    }
}

// ---------------- KO5: fused Z sweep (phase A) + pipelined S/O sweep (phase B) ----------------
struct Ko5Smem {
    unsigned ksh[128 * 20];
    unsigned ksl[128 * 20];
    unsigned qsh[2][64 * 20];
    unsigned qsl[2][64 * 20];
    unsigned As[128 * 36];     // bf16 P tile (single buffer; protected by 2 bars/iter)
    unsigned Bs[2][256 * 36];  // v chunks; phase-A q buffers; epilogue fp32 staging
    float AMs[128 * 68];       // normalized P staging
    float zsh[128];
};
#define QBUF_B (64 * 20 * 4)
#define VBUF_B (256 * 36 * 4)
#define PA_BUF (2 * 128 * 20 * 4)
#define PA_HL  (128 * 20 * 4)

__global__ void __launch_bounds__(512) k_o5(float* __restrict__ AM, const float* __restrict__ x,
                                            const float* __restrict__ gptr, float* __restrict__ outp) {
    extern __shared__ Ko5Smem s5[];
    Ko5Smem& S = s5[0];
    int jb = blockIdx.x, b = blockIdx.y;
    int j0 = jb * 128;
    int tid = threadIdx.x;
    if (tid < 128) S.zsh[tid] = 0.f;
    // K tiles once
    for (int u = tid; u < 1024; u += 512) {
        int bufl = u >> 9, r = (u >> 2) & 127, w = (u & 3) * 4;
        const unsigned* src = (bufl ? g_kl : g_kh) + ((size_t)b * NN + j0 + r) * 16 + w;
        unsigned* dst = (bufl ? S.ksl : S.ksh) + r * 20 + w;
        *(uint4*)dst = *(const uint4*)src;
    }
    __syncthreads();

    int warp = tid >> 5, lane = tid & 31, gid = lane >> 2, tg = lane & 3;
    int j0s = (warp & 7) * 16;
    int m0sB = (warp >> 3) * 32, m0sA = (warp >> 3) * 64;
    int wj = warp >> 2, wc = warp & 3;
    unsigned aoffS = ((j0s + (lane & 15)) * 20 + ((lane >> 4) << 2)) * 4;
    unsigned kshA = sptr(S.ksh) + aoffS, kslA = sptr(S.ksl) + aoffS;
    unsigned boffS = (((lane & 7) + ((lane & 16) >> 1)) * 20 + ((lane & 8) >> 1)) * 4;
    unsigned AsA = sptr(S.As) + ((lane & 15) * 36 + ((lane >> 4) << 2)) * 4;
    unsigned boffO = ((((lane & 7) + ((lane & 16) >> 1)) + wc * 64) * 36 + ((lane & 8) >> 1)) * 4;
    unsigned qshS = sptr(S.qsh[0]), qslS = sptr(S.qsl[0]), BsS = sptr(S.Bs[0]);
    const unsigned* vbp = g_vtp + (size_t)b * CC * (NN / 2);

    // hoisted k A-fragments (loop-invariant across BOTH phases)
    unsigned ah2[2][4], al2[2][4];
    ldsm4(kshA + 0, ah2[0][0], ah2[0][1], ah2[0][2], ah2[0][3]);
    ldsm4(kshA + 32, ah2[1][0], ah2[1][1], ah2[1][2], ah2[1][3]);
    ldsm4(kslA + 0, al2[0][0], al2[0][1], al2[0][2], al2[0][3]);
    ldsm4(kslA + 32, al2[1][0], al2[1][1], al2[1][2], al2[1][3]);

    // ================= phase A: Z sweep (q streamed in 128-row chunks into Bs region) ================
    {
        for (int u = tid; u < 1024; u += 512) {
            int hl = u >> 9, r = (u >> 2) & 127, w4 = (u & 3) * 4;
            cpa16(BsS + hl * PA_HL + (r * 20 + w4) * 4,
                  (hl ? g_ql : g_qh) + ((size_t)b * NN + r) * 16 + w4);
        }
        asm volatile("cp.async.commit_group;");
    }
    float z0 = 0.f, z1 = 0.f;
    for (int it = 0; it < 32; it++) {
        if (it < 31) {
            int i0n = (it + 1) * 128;
            for (int u = tid; u < 1024; u += 512) {
                int hl = u >> 9, r = (u >> 2) & 127, w4 = (u & 3) * 4;
                cpa16(BsS + ((it + 1) & 1) * PA_BUF + hl * PA_HL + (r * 20 + w4) * 4,
                      (hl ? g_ql : g_qh) + ((size_t)b * NN + i0n + r) * 16 + w4);
            }
        }
        asm volatile("cp.async.commit_group;");
        asm volatile("cp.async.wait_group 1;");
        __syncthreads();
        unsigned qh_b = BsS + (it & 1) * PA_BUF + boffS;
        unsigned ql_b = qh_b + PA_HL;
#pragma unroll
        for (int tp = 0; tp < 8; tp += 2) {
            float d2[2][4];
#pragma unroll
            for (int a = 0; a < 2; a++)
#pragma unroll
                for (int e = 0; e < 4; e++) d2[a][e] = 0.f;
#pragma unroll
            for (int kk2 = 0; kk2 < 2; kk2++) {
                unsigned ro = (unsigned)((m0sA + tp * 8) * 80) + kk2 * 32;
                unsigned bh0, bh1, bh2, bh3, bl0, bl1, bl2, bl3;
                ldsm4(qh_b + ro, bh0, bh1, bh2, bh3);
                ldsm4(ql_b + ro, bl0, bl1, bl2, bl3);
                mma16816(d2[0], ah2[kk2][0], ah2[kk2][1], ah2[kk2][2], ah2[kk2][3], bh0, bh1);
                mma16816(d2[0], ah2[kk2][0], ah2[kk2][1], ah2[kk2][2], ah2[kk2][3], bl0, bl1);
                mma16816(d2[0], al2[kk2][0], al2[kk2][1], al2[kk2][2], al2[kk2][3], bh0, bh1);
                mma16816(d2[1], ah2[kk2][0], ah2[kk2][1], ah2[kk2][2], ah2[kk2][3], bh2, bh3);
                mma16816(d2[1], ah2[kk2][0], ah2[kk2][1], ah2[kk2][2], ah2[kk2][3], bl2, bl3);
                mma16816(d2[1], al2[kk2][0], al2[kk2][1], al2[kk2][2], al2[kk2][3], bh2, bh3);
            }
            z0 += ex2f(d2[0][0]) + ex2f(d2[0][1]) + ex2f(d2[1][0]) + ex2f(d2[1][1]);
            z1 += ex2f(d2[0][2]) + ex2f(d2[0][3]) + ex2f(d2[1][2]) + ex2f(d2[1][3]);
        }
    }
    z0 += __shfl_xor_sync(0xffffffffu, z0, 1);
    z0 += __shfl_xor_sync(0xffffffffu, z0, 2);
    z1 += __shfl_xor_sync(0xffffffffu, z1, 1);
    z1 += __shfl_xor_sync(0xffffffffu, z1, 2);
    if (tg == 0) {
        atomicAdd(&S.zsh[j0s + gid], z0);
        atomicAdd(&S.zsh[j0s + gid + 8], z1);
    }
    asm volatile("cp.async.wait_group 0;");
    __syncthreads();
    float rz0 = 1.f / S.zsh[j0s + gid], rz1 = 1.f / S.zsh[j0s + gid + 8];

    // ================= phase B: pipelined S(t) + O(t-1) ================
    float acc[2][8][4];
#pragma unroll
    for (int a = 0; a < 2; a++)
#pragma unroll
        for (int n = 0; n < 8; n++)
#pragma unroll
            for (int c = 0; c < 4; c++) acc[a][n][c] = 0.f;
    float* AMrow = AM + ((size_t)b * NN + j0) * (size_t)NN;
    int qlf = tid >> 8, qlr = (tid >> 2) & 63, qlw = (tid & 3) * 4;
    {  // prologue: q(0)
        cpa16((qlf ? qslS : qshS) + (qlr * 20 + qlw) * 4,
              (qlf ? g_ql : g_qh) + ((size_t)b * NN + qlr) * 16 + qlw);
        asm volatile("cp.async.commit_group;");
    }
    for (int t = 0; t < 64; t++) {
        int bb = t & 1;
        int m0 = t * 64;
        if (t < 63) {
            const unsigned* qs = (qlf ? g_ql : g_qh) + ((size_t)b * NN + (m0 + 64) + qlr) * 16 + qlw;
            cpa16((qlf ? qslS : qshS) + (bb ^ 1) * QBUF_B + (qlr * 20 + qlw) * 4, qs);
        }
#pragma unroll
        for (int itv = 0; itv < 4; itv++) {
            int idx = itv * 512 + tid;
            int r = idx >> 3, ch = (idx & 7) * 4;
            cpa16(BsS + bb * VBUF_B + (r * 36 + ch) * 4,
                  vbp + (size_t)r * (NN / 2) + (m0 >> 1) + ch);
        }
        asm volatile("cp.async.commit_group;");
        asm volatile("cp.async.wait_group 1;");
        __syncthreads();  // barA
        // ---- S-mma(t) ----
        unsigned qshB = qshS + bb * QBUF_B + boffS;
        unsigned qslB = qslS + bb * QBUF_B + boffS;
        float d[4][4];
#pragma unroll
        for (int tt = 0; tt < 4; tt++)
#pragma unroll
            for (int e = 0; e < 4; e++) d[tt][e] = 0.f;
#pragma unroll
        for (int kk2 = 0; kk2 < 2; kk2++) {
#pragma unroll
            for (int tp = 0; tp < 4; tp += 2) {
                unsigned ro = (unsigned)((m0sB + tp * 8) * 80) + kk2 * 32;
                unsigned bh0, bh1, bh2, bh3, bl0, bl1, bl2, bl3;
                ldsm4(qshB + ro, bh0, bh1, bh2, bh3);
                ldsm4(qslB + ro, bl0, bl1, bl2, bl3);
                mma16816(d[tp], ah2[kk2][0], ah2[kk2][1], ah2[kk2][2], ah2[kk2][3], bh0, bh1);
                mma16816(d[tp], ah2[kk2][0], ah2[kk2][1], ah2[kk2][2], ah2[kk2][3], bl0, bl1);
                mma16816(d[tp], al2[kk2][0], al2[kk2][1], al2[kk2][2], al2[kk2][3], bh0, bh1);
                mma16816(d[tp + 1], ah2[kk2][0], ah2[kk2][1], ah2[kk2][2], ah2[kk2][3], bh2, bh3);
                mma16816(d[tp + 1], ah2[kk2][0], ah2[kk2][1], ah2[kk2][2], ah2[kk2][3], bl2, bl3);
                mma16816(d[tp + 1], al2[kk2][0], al2[kk2][1], al2[kk2][2], al2[kk2][3], bh2, bh3);
            }
        }
        // ---- O-mma(t-1) + AM store(t-1): hides the d-latency, fills tensor pipe ----
        if (t > 0) {
            unsigned BsB = BsS + (bb ^ 1) * VBUF_B + boffO;
#pragma unroll
            for (int kk = 0; kk < 4; kk++) {
                unsigned a0[4], a1[4];
                ldsm4(AsA + (unsigned)((wj * 32) * 144 + kk * 32), a0[0], a0[1], a0[2], a0[3]);
                ldsm4(AsA + (unsigned)((wj * 32 + 16) * 144 + kk * 32), a1[0], a1[1], a1[2], a1[3]);
#pragma unroll
                for (int ntp = 0; ntp < 4; ntp++) {
                    unsigned b0a, b1a, b0b, b1b;
                    ldsm4(BsB + (unsigned)((ntp * 16) * 144 + kk * 32), b0a, b1a, b0b, b1b);
                    mma16816(acc[0][2 * ntp], a0[0], a0[1], a0[2], a0[3], b0a, b1a);
                    mma16816(acc[1][2 * ntp], a1[0], a1[1], a1[2], a1[3], b0a, b1a);
                    mma16816(acc[0][2 * ntp + 1], a0[0], a0[1], a0[2], a0[3], b0b, b1b);
                    mma16816(acc[1][2 * ntp + 1], a1[0], a1[1], a1[2], a1[3], b0b, b1b);
                }
            }
            int m0p = m0 - 64;
            for (int u = tid; u < 2048; u += 512) {
                int r = u >> 4, g4 = u & 15;
                *(float4*)&AMrow[(size_t)r * NN + m0p + g4 * 4] = *(float4*)&S.AMs[r * 68 + g4 * 4];
            }
        }
        __syncthreads();  // barB
        // ---- exp + normalize + stage ----
#pragma unroll
        for (int tt = 0; tt < 4; tt++) {
            float e0 = ex2f(d[tt][0]) * rz0;
            float e1 = ex2f(d[tt][1]) * rz0;
            float e2 = ex2f(d[tt][2]) * rz1;
            float e3 = ex2f(d[tt][3]) * rz1;
            int col = m0sB + tt * 8 + 2 * tg;
            *(float2*)&S.AMs[(j0s + gid) * 68 + col] = make_float2(e0, e1);
            *(float2*)&S.AMs[(j0s + gid + 8) * 68 + col] = make_float2(e2, e3);
            S.As[(j0s + gid) * 36 + (m0sB >> 1) + tt * 4 + tg] = bf16bits(e0) | (bf16bits(e1) << 16);
            S.As[(j0s + gid + 8) * 36 + (m0sB >> 1) + tt * 4 + tg] = bf16bits(e2) | (bf16bits(e3) << 16);
        }
    }
    // ---- drain: O(63) + AM(63) ----
    asm volatile("cp.async.wait_group 0;");
    __syncthreads();
    {
        unsigned BsB = BsS + 1 * VBUF_B + boffO;
#pragma unroll
        for (int kk = 0; kk < 4; kk++) {
            unsigned a0[4], a1[4];
            ldsm4(AsA + (unsigned)((wj * 32) * 144 + kk * 32), a0[0], a0[1], a0[2], a0[3]);
            ldsm4(AsA + (unsigned)((wj * 32 + 16) * 144 + kk * 32), a1[0], a1[1], a1[2], a1[3]);
#pragma unroll
            for (int ntp = 0; ntp < 4; ntp++) {
                unsigned b0a, b1a, b0b, b1b;
                ldsm4(BsB + (unsigned)((ntp * 16) * 144 + kk * 32), b0a, b1a, b0b, b1b);
                mma16816(acc[0][2 * ntp], a0[0], a0[1], a0[2], a0[3], b0a, b1a);
                mma16816(acc[1][2 * ntp], a1[0], a1[1], a1[2], a1[3], b0a, b1a);
                mma16816(acc[0][2 * ntp + 1], a0[0], a0[1], a0[2], a0[3], b0b, b1b);
                mma16816(acc[1][2 * ntp + 1], a1[0], a1[1], a1[2], a1[3], b0b, b1b);
            }
        }
        for (int u = tid; u < 2048; u += 512) {
            int r = u >> 4, g4 = u & 15;
            *(float4*)&AMrow[(size_t)r * NN + 4032 + g4 * 4] = *(float4*)&S.AMs[r * 68 + g4 * 4];
        }
    }
    __syncthreads();
    // ---- epilogue: out = x + gamma*o ----
    float gma = __ldg(gptr);
    float* fBs = (float*)S.Bs[0];  // 32 x 256 fp32
    int ec = tid & 255, ejh = tid >> 8;
    for (int h = 0; h < 4; h++) {
        if (wj == h) {
#pragma unroll
            for (int jt = 0; jt < 2; jt++)
#pragma unroll
                for (int nt = 0; nt < 8; nt++) {
                    int rr = jt * 16 + gid;
                    int cc2 = wc * 64 + nt * 8 + tg * 2;
                    fBs[rr * 256 + cc2]           = acc[jt][nt][0];
                    fBs[rr * 256 + cc2 + 1]       = acc[jt][nt][1];
                    fBs[(rr + 8) * 256 + cc2]     = acc[jt][nt][2];
                    fBs[(rr + 8) * 256 + cc2 + 1] = acc[jt][nt][3];
                }
        }
        __syncthreads();
        const float* xrow = x + ((size_t)b * CC + ec) * NN + j0 + h * 32 + ejh * 16;
        float* orow = outp + ((size_t)b * CC + ec) * NN + j0 + h * 32 + ejh * 16;
#pragma unroll
        for (int jq = 0; jq < 4; jq++) {
            float4 o;
            o.x = fBs[(ejh * 16 + jq * 4 + 0) * 256 + ec];
            o.y = fBs[(ejh * 16 + jq * 4 + 1) * 256 + ec];
            o.z = fBs[(ejh * 16 + jq * 4 + 2) * 256 + ec];
            o.w = fBs[(ejh * 16 + jq * 4 + 3) * 256 + ec];
            float4 xr = *(const float4*)(xrow + jq * 4);
            float4 res = {xr.x + gma * o.x, xr.y + gma * o.y, xr.z + gma * o.z, xr.w + gma * o.w};
            *(float4*)(orow + jq * 4) = res;
        }
        __syncthreads();
    }
}

// ---------------- launch ----------------
extern "C" void kernel_launch(void* const* d_in, const int* in_sizes, int n_in,
                              void* d_out, int out_size) {
    const float* x  = (const float*)d_in[0];
    const float* Wq = (const float*)d_in[1];
    const float* bq = (const float*)d_in[2];
    const float* Wk = (const float*)d_in[3];
    const float* bk = (const float*)d_in[4];
    const float* Wv = (const float*)d_in[5];
    const float* bv = (const float*)d_in[6];
    const float* gm = (const float*)d_in[7];
    float* outp = (float*)d_out;
    float* AM = outp + (size_t)BN * CC * 64 * 64;

    cudaFuncSetAttribute(k_o5, cudaFuncAttributeMaxDynamicSharedMemorySize,
                         (int)sizeof(Ko5Smem));

    k_qk<<<dim3(64, BN), 256>>>(x, Wq, bq, Wk, bk);
    k_v<<<dim3(128, BN), 256>>>(x, Wv, bv);
    k_o5<<<dim3(32, BN), 512, sizeof(Ko5Smem)>>>(AM, x, gm, outp);
}